// round 13
// baseline (speedup 1.0000x reference)
#include <cuda_runtime.h>
#include <cuda_fp16.h>
#include <math.h>
#include <stdint.h>

#define EMBED   1024
#define HEADS   16
#define HD      64
#define NB      12
#define SEQ     257
#define BATCH   32
#define MROWS   (BATCH*SEQ)      // 8224
#define HIDDEN  2816

// ---------------- scratch (device globals; no allocations allowed) ----------
__device__ __align__(256) __half g_a[MROWS*EMBED];      // rmsnorm out (half, GEMM A)
__device__ __align__(256) __half g_o[MROWS*EMBED];      // attn out (half, GEMM A)
__device__ __align__(256) __half g_u[MROWS*HIDDEN];     // silu(u)*v (half, GEMM A)
__device__ __align__(256) __half g_xh[8192*768];        // x (half)
__device__ __align__(256) __half g_ch[32*1024];         // cond (half)
__device__ __align__(256) float  g_qkv[MROWS*3*EMBED];  // qkv (raw) / cond-out (f32)
__device__ __align__(256) float  g_f1[MROWS*HIDDEN];    // w1-out / patch-out (f32)
__device__ __align__(256) float  g_fc[SEQ*32*2];        // rope cos/sin table

// half weights, k-pair interleaved: [K/2][N] half2
#define OFF_QKV   ((size_t)0)
#define OFF_WO    (OFF_QKV + (size_t)NB*1024*3072)
#define OFF_W1    (OFF_WO  + (size_t)NB*1024*1024)
#define OFF_W3    (OFF_W1  + (size_t)NB*1024*HIDDEN)
#define OFF_W2    (OFF_W3  + (size_t)NB*1024*HIDDEN)
#define OFF_PATCH (OFF_W2  + (size_t)NB*HIDDEN*1024)
#define OFF_COND  (OFF_PATCH + (size_t)768*1024)
#define WT_TOTAL  (OFF_COND + (size_t)1024*1024)
__device__ __align__(256) __half g_wt[WT_TOTAL];

// attention warp->q-tile schedule (chunk-balanced 38/38/39/38)
__constant__ int g_wtiles[20] = {16,12,5,1,-1, 15,13,4,2,-1, 14,11,6,3,0, 10,9,8,7,-1};

// ---------------- helpers ----------------------------------------------------
__device__ __forceinline__ uint32_t smem_u32(const void* p) {
    uint32_t a;
    asm("{ .reg .u64 t; cvta.to.shared.u64 t, %1; cvt.u32.u64 %0, t; }" : "=r"(a) : "l"(p));
    return a;
}

__device__ __forceinline__ uint32_t pack_h2(float a, float b) {
    __half2 h = __floats2half2_rn(a, b);
    return *(uint32_t*)&h;
}

__device__ __forceinline__ void mma_f16(float c[4], const uint32_t a[4],
                                        const uint32_t b[2]) {
    asm volatile(
        "mma.sync.aligned.m16n8k16.row.col.f32.f16.f16.f32 "
        "{%0,%1,%2,%3}, {%4,%5,%6,%7}, {%8,%9}, {%0,%1,%2,%3};"
        : "+f"(c[0]), "+f"(c[1]), "+f"(c[2]), "+f"(c[3])
        : "r"(a[0]), "r"(a[1]), "r"(a[2]), "r"(a[3]), "r"(b[0]), "r"(b[1]));
}

__device__ __forceinline__ void cp16(uint32_t dst, const void* src, int sz) {
    asm volatile("cp.async.cg.shared.global [%0], [%1], 16, %2;"
        :: "r"(dst), "l"(src), "r"(sz) : "memory");
}

// ---------------- pipelined FP16 tensor-core GEMM ----------------------------
// Template-specialized epilogues (compile-time, separate kernels; EPI=0 path
// is the R10/R12-proven kernel with dead branches removed):
//   EPI=0: C(f32) = acc (+bias) (+res)
//   EPI=1: outH(half) = silu(gate) * acc      (w3 GEMM)
#define BM     128
#define BN     128
#define BK     64
#define A_SW   36
#define B_SW   136
#define A_WORDS (BM*A_SW)
#define B_WORDS ((BK/2)*B_SW)
#define ST_WORDS (A_WORDS+B_WORDS)
#define G_SMEM (3*ST_WORDS*4)

template<int EPI>
__global__ __launch_bounds__(128) void ar_gemm_f16(
    const __half* __restrict__ A, const __half2* __restrict__ B2,
    const float* __restrict__ bias, const float* __restrict__ res,
    float* __restrict__ C, const float* __restrict__ gate,
    __half* __restrict__ outH, int M, int N, int K)
{
    extern __shared__ uint32_t sm[];
    uint32_t sm_u = smem_u32(sm);

    int tid = threadIdx.x, lane = tid & 31, warp = tid >> 5;
    int wm = warp & 1, wn = warp >> 1;
    int bm = blockIdx.y * BM, bn = blockIdx.x * BN;
    int g = lane >> 2, tg = lane & 3;

    float acc[4][8][4];
    #pragma unroll
    for (int i = 0; i < 4; i++)
        #pragma unroll
        for (int j = 0; j < 8; j++)
            #pragma unroll
            for (int t = 0; t < 4; t++) acc[i][j][t] = 0.f;

    const int NC = K / BK;

    auto load_chunk = [&](int cidx) {
        int s = cidx % 3;
        int k0 = cidx * BK;
        uint32_t st = sm_u + (uint32_t)(s * ST_WORDS) * 4u;
        #pragma unroll
        for (int i = 0; i < 8; i++) {
            int idx = tid + (i << 7);
            int r = idx >> 3, cc = idx & 7;
            uint32_t dst = st + (uint32_t)(r * A_SW + cc * 4) * 4u;
            int gm = bm + r;
            bool v = (gm < M);
            const __half* src = A + (size_t)(v ? gm : 0) * K + k0 + cc * 8;
            cp16(dst, src, v ? 16 : 0);
        }
        #pragma unroll
        for (int i = 0; i < 8; i++) {
            int idx = tid + (i << 7);
            int r = idx >> 5, cc = idx & 31;
            uint32_t dst = st + (uint32_t)(A_WORDS + r * B_SW + cc * 4) * 4u;
            const __half2* src = B2 + (size_t)(k0 / 2 + r) * N + bn + cc * 4;
            cp16(dst, src, 16);
        }
    };

    auto compute = [&](int s) {
        const uint32_t* St = sm + s * ST_WORDS;
        const uint32_t* Ab = St;
        const uint32_t* Bb = St + A_WORDS;
        int m0 = wm * 64 + g;
        int n0 = wn * 64 + g;
        #pragma unroll
        for (int ks = 0; ks < 4; ks++) {
            int kw = ks * 8;
            uint32_t af[4][4];
            #pragma unroll
            for (int mt = 0; mt < 4; mt++) {
                int base = (m0 + mt * 16) * A_SW + kw + tg;
                af[mt][0] = Ab[base];
                af[mt][1] = Ab[base + 8 * A_SW];
                af[mt][2] = Ab[base + 4];
                af[mt][3] = Ab[base + 8 * A_SW + 4];
            }
            uint32_t bf[8][2];
            #pragma unroll
            for (int nt = 0; nt < 8; nt++) {
                int bb = (kw + tg) * B_SW + n0 + nt * 8;
                bf[nt][0] = Bb[bb];
                bf[nt][1] = Bb[bb + 4 * B_SW];
            }
            #pragma unroll
            for (int mt = 0; mt < 4; mt++)
                #pragma unroll
                for (int nt = 0; nt < 8; nt++)
                    mma_f16(acc[mt][nt], af[mt], bf[nt]);
        }
    };

    load_chunk(0);
    asm volatile("cp.async.commit_group;" ::: "memory");
    load_chunk(1);
    asm volatile("cp.async.commit_group;" ::: "memory");
    load_chunk(2);
    asm volatile("cp.async.commit_group;" ::: "memory");

    for (int c = 0; c < NC; c++) {
        asm volatile("cp.async.wait_group 2;" ::: "memory");
        __syncthreads();
        compute(c % 3);
        __syncthreads();
        if (c + 3 < NC) load_chunk(c + 3);
        asm volatile("cp.async.commit_group;" ::: "memory");
    }

    #pragma unroll
    for (int mt = 0; mt < 4; mt++) {
        int rbase = bm + wm * 64 + mt * 16 + g;
        #pragma unroll
        for (int half = 0; half < 2; half++) {
            int r = rbase + half * 8;
            if (r >= M) continue;
            #pragma unroll
            for (int nt = 0; nt < 8; nt++) {
                int cl = bn + wn * 64 + nt * 8 + 2 * tg;
                float2 v;
                v.x = acc[mt][nt][half * 2 + 0];
                v.y = acc[mt][nt][half * 2 + 1];
                if (EPI == 0) {
                    if (bias) { v.x += bias[cl]; v.y += bias[cl + 1]; }
                    if (res) {
                        float2 rr = *(const float2*)(res + (size_t)r * N + cl);
                        v.x += rr.x; v.y += rr.y;
                    }
                    *(float2*)(C + (size_t)r * N + cl) = v;
                } else {
                    float2 gg = *(const float2*)(gate + (size_t)r * N + cl);
                    float s0 = gg.x / (1.f + __expf(-gg.x)) * v.x;
                    float s1 = gg.y / (1.f + __expf(-gg.y)) * v.y;
                    *(__half2*)(outH + (size_t)r * N + cl) = __floats2half2_rn(s0, s1);
                }
            }
        }
    }
}

// ---------------- tensor-core flash attention with fused rope ----------------
// One block per (b,h). Rope applied inline (f32, identical order to ar_rope)
// on the K smem fill and Q fragment loads. V untouched.
#define KH_WORDS (264*36)
#define VT_WORDS (64*140)
#define ATT_SMEM ((KH_WORDS+VT_WORDS)*4)

__global__ __launch_bounds__(128) void ar_fattn(const float* __restrict__ qkv,
                                                const float* __restrict__ fc,
                                                __half* __restrict__ o)
{
    extern __shared__ uint32_t smw[];
    uint32_t* KhW = smw;
    uint32_t* VtW = smw + KH_WORDS;
    int h = blockIdx.x, b = blockIdx.y;
    int tid = threadIdx.x, lane = tid & 31, warp = tid >> 5;
    int g = lane >> 2, tg = lane & 3;

    #pragma unroll 8
    for (int i = tid; i < KH_WORDS + VT_WORDS; i += 128) smw[i] = 0;
    __syncthreads();

    const float* kbase = qkv + (size_t)b * SEQ * 3072 + 1024 + h * 64;
    #pragma unroll 4
    for (int idx = tid; idx < 257 * 16; idx += 128) {
        int s_ = idx >> 4, c = idx & 15;
        float4 kv = *(const float4*)(kbase + (size_t)s_ * 3072 + c * 4);
        // rope pairs (kv.x,kv.y) @ j=2c and (kv.z,kv.w) @ j=2c+1
        const float* f0 = fc + (s_ * 32 + 2 * c) * 2;
        float c0 = f0[0], s0 = f0[1], c1 = f0[2], s1 = f0[3];
        float r0 = kv.x * c0 - kv.y * s0, r1 = kv.y * c0 + kv.x * s0;
        float r2 = kv.z * c1 - kv.w * s1, r3 = kv.w * c1 + kv.z * s1;
        *(uint2*)&KhW[s_ * 36 + 2 * c] = make_uint2(pack_h2(r0, r1), pack_h2(r2, r3));
    }
    const float* vbase = kbase + 1024;
    {
        int d = tid & 63;
        #pragma unroll 4
        for (int jp = tid >> 6; jp < 129; jp += 2) {
            int j0 = 2 * jp, j1 = j0 + 1;
            float v0 = vbase[(size_t)j0 * 3072 + d];
            float v1 = (j1 < 257) ? vbase[(size_t)j1 * 3072 + d] : 0.f;
            VtW[d * 140 + jp] = pack_h2(v0, v1);
        }
    }
    __syncthreads();

    for (int ti = 0; ti < 5; ti++) {
        int t = g_wtiles[warp * 5 + ti];
        if (t < 0) break;
        int q0 = t * 16;

        uint32_t aq[4][4];
        int r0c = min(q0 + g, 256), r1c = min(q0 + g + 8, 256);
        const float* q0p = qkv + (size_t)(b * SEQ + r0c) * 3072 + h * 64;
        const float* q1p = qkv + (size_t)(b * SEQ + r1c) * 3072 + h * 64;
        #pragma unroll
        for (int s = 0; s < 4; s++) {
            int dlo = s * 16 + 2 * tg, dhi = dlo + 8;
            int jlo = dlo >> 1, jhi = dhi >> 1;
            float cl0 = fc[(r0c * 32 + jlo) * 2],  sl0 = fc[(r0c * 32 + jlo) * 2 + 1];
            float ch0 = fc[(r0c * 32 + jhi) * 2],  sh0 = fc[(r0c * 32 + jhi) * 2 + 1];
            float cl1 = fc[(r1c * 32 + jlo) * 2],  sl1 = fc[(r1c * 32 + jlo) * 2 + 1];
            float ch1 = fc[(r1c * 32 + jhi) * 2],  sh1 = fc[(r1c * 32 + jhi) * 2 + 1];
            float2 v;
            v = *(const float2*)(q0p + dlo);
            aq[s][0] = pack_h2((v.x * cl0 - v.y * sl0) * 0.125f,
                               (v.y * cl0 + v.x * sl0) * 0.125f);
            v = *(const float2*)(q1p + dlo);
            aq[s][1] = pack_h2((v.x * cl1 - v.y * sl1) * 0.125f,
                               (v.y * cl1 + v.x * sl1) * 0.125f);
            v = *(const float2*)(q0p + dhi);
            aq[s][2] = pack_h2((v.x * ch0 - v.y * sh0) * 0.125f,
                               (v.y * ch0 + v.x * sh0) * 0.125f);
            v = *(const float2*)(q1p + dhi);
            aq[s][3] = pack_h2((v.x * ch1 - v.y * sh1) * 0.125f,
                               (v.y * ch1 + v.x * sh1) * 0.125f);
        }

        float m0 = -1e30f, m1 = -1e30f, l0 = 0.f, l1 = 0.f;
        float acc[8][4];
        #pragma unroll
        for (int nt = 0; nt < 8; nt++)
            #pragma unroll
            for (int q = 0; q < 4; q++) acc[nt][q] = 0.f;

        int row0 = q0 + g, row1 = row0 + 8;
        int nchunks = t + 1;
        for (int ch = 0; ch < nchunks; ch++) {
            int j0c = ch * 16;
            float sc0[4] = {0.f, 0.f, 0.f, 0.f};
            float sc1[4] = {0.f, 0.f, 0.f, 0.f};
            #pragma unroll
            for (int s = 0; s < 4; s++) {
                uint32_t b0[2], b1[2];
                int base0 = (j0c + g) * 36 + 8 * s + tg;
                b0[0] = KhW[base0];
                b0[1] = KhW[base0 + 4];
                b1[0] = KhW[base0 + 8 * 36];
                b1[1] = KhW[base0 + 8 * 36 + 4];
                mma_f16(sc0, aq[s], b0);
                mma_f16(sc1, aq[s], b1);
            }
            if (ch == t) {
                int cb = j0c + 2 * tg;
                if (cb     > row0) sc0[0] = -1e30f;
                if (cb + 1 > row0) sc0[1] = -1e30f;
                if (cb     > row1) sc0[2] = -1e30f;
                if (cb + 1 > row1) sc0[3] = -1e30f;
                if (cb + 8 > row0) sc1[0] = -1e30f;
                if (cb + 9 > row0) sc1[1] = -1e30f;
                if (cb + 8 > row1) sc1[2] = -1e30f;
                if (cb + 9 > row1) sc1[3] = -1e30f;
            }
            float cm0 = fmaxf(fmaxf(sc0[0], sc0[1]), fmaxf(sc1[0], sc1[1]));
            float cm1 = fmaxf(fmaxf(sc0[2], sc0[3]), fmaxf(sc1[2], sc1[3]));
            cm0 = fmaxf(cm0, __shfl_xor_sync(0xffffffffu, cm0, 1));
            cm0 = fmaxf(cm0, __shfl_xor_sync(0xffffffffu, cm0, 2));
            cm1 = fmaxf(cm1, __shfl_xor_sync(0xffffffffu, cm1, 1));
            cm1 = fmaxf(cm1, __shfl_xor_sync(0xffffffffu, cm1, 2));
            float nm0 = fmaxf(m0, cm0), nm1 = fmaxf(m1, cm1);
            float corr0 = __expf(m0 - nm0), corr1 = __expf(m1 - nm1);
            float p00 = __expf(sc0[0] - nm0), p01 = __expf(sc0[1] - nm0);
            float p02 = __expf(sc0[2] - nm1), p03 = __expf(sc0[3] - nm1);
            float p10 = __expf(sc1[0] - nm0), p11 = __expf(sc1[1] - nm0);
            float p12 = __expf(sc1[2] - nm1), p13 = __expf(sc1[3] - nm1);
            float ps0 = (p00 + p01) + (p10 + p11);
            float ps1 = (p02 + p03) + (p12 + p13);
            ps0 += __shfl_xor_sync(0xffffffffu, ps0, 1);
            ps0 += __shfl_xor_sync(0xffffffffu, ps0, 2);
            ps1 += __shfl_xor_sync(0xffffffffu, ps1, 1);
            ps1 += __shfl_xor_sync(0xffffffffu, ps1, 2);
            l0 = l0 * corr0 + ps0;
            l1 = l1 * corr1 + ps1;
            m0 = nm0; m1 = nm1;

            uint32_t ap[4];
            ap[0] = pack_h2(p00, p01);
            ap[1] = pack_h2(p02, p03);
            ap[2] = pack_h2(p10, p11);
            ap[3] = pack_h2(p12, p13);

            int jh = (j0c >> 1) + tg;
            #pragma unroll
            for (int nt = 0; nt < 8; nt++) {
                acc[nt][0] *= corr0; acc[nt][1] *= corr0;
                acc[nt][2] *= corr1; acc[nt][3] *= corr1;
                uint32_t bv[2];
                int vb = (nt * 8 + g) * 140 + jh;
                bv[0] = VtW[vb];
                bv[1] = VtW[vb + 4];
                mma_f16(acc[nt], ap, bv);
            }
        }

        float inv0 = 1.f / l0, inv1 = 1.f / l1;
        __half* ob = o + (size_t)b * SEQ * EMBED + h * 64 + 2 * tg;
        if (row0 < SEQ) {
            __half* orow = ob + (size_t)row0 * EMBED;
            #pragma unroll
            for (int nt = 0; nt < 8; nt++)
                *(__half2*)(orow + nt * 8) =
                    __floats2half2_rn(acc[nt][0] * inv0, acc[nt][1] * inv0);
        }
        if (row1 < SEQ) {
            __half* orow = ob + (size_t)row1 * EMBED;
            #pragma unroll
            for (int nt = 0; nt < 8; nt++)
                *(__half2*)(orow + nt * 8) =
                    __floats2half2_rn(acc[nt][2] * inv1, acc[nt][3] * inv1);
        }
    }
}

// ---------------- weight convert: [K][N] f32 -> [K/2][N] half2 (wide) --------
__global__ __launch_bounds__(256) void ar_b2h(const float* __restrict__ in,
                                              __half2* __restrict__ out,
                                              int K, int N) {
    size_t z = blockIdx.z;
    in  += z * (size_t)K * N;
    out += z * (size_t)(K / 2) * N;
    int total = (K / 2) * (N / 4);
    int idx = blockIdx.x * blockDim.x + threadIdx.x;
    if (idx >= total) return;
    int nq = N / 4;
    int k2 = idx / nq, n4 = (idx - k2 * nq) * 4;
    float4 lo = *(const float4*)(in + (size_t)(2 * k2) * N + n4);
    float4 hi = *(const float4*)(in + (size_t)(2 * k2 + 1) * N + n4);
    __half2* op = out + (size_t)k2 * N + n4;
    op[0] = __floats2half2_rn(lo.x, hi.x);
    op[1] = __floats2half2_rn(lo.y, hi.y);
    op[2] = __floats2half2_rn(lo.z, hi.z);
    op[3] = __floats2half2_rn(lo.w, hi.w);
}

// ---------------- activation convert: f32 -> f16 flat ------------------------
__global__ void ar_f2h(const float* __restrict__ in, __half2* __restrict__ out,
                       size_t n4) {
    size_t i = (size_t)blockIdx.x * blockDim.x + threadIdx.x;
    if (i < n4) {
        float4 v = ((const float4*)in)[i];
        out[2 * i]     = __floats2half2_rn(v.x, v.y);
        out[2 * i + 1] = __floats2half2_rn(v.z, v.w);
    }
}

// ---------------- reductions ------------------------------------------------
__device__ __forceinline__ float block_sum(float v, float* red) {
    int tid = threadIdx.x;
    #pragma unroll
    for (int o = 16; o > 0; o >>= 1) v += __shfl_xor_sync(0xffffffffu, v, o);
    if ((tid & 31) == 0) red[tid >> 5] = v;
    __syncthreads();
    if (tid == 0) {
        float s = red[0];
        int nw = blockDim.x >> 5;
        for (int i = 1; i < nw; i++) s += red[i];
        red[0] = s;
    }
    __syncthreads();
    float r = red[0];
    __syncthreads();
    return r;
}

// ---------------- rope frequency table --------------------------------------
__global__ void ar_freqs(float* __restrict__ fc) {
    int t = blockIdx.x * blockDim.x + threadIdx.x;
    if (t >= SEQ * 32) return;
    int p = t >> 5, j = t & 31;
    float c = 0.f, s = 0.f;
    if (p > 0) {                       // cls token keeps cos=sin=0 (ref!)
        int pp = p - 1, yy = pp >> 4, xx = pp & 15;
        int i = j & 15;
        float fr = powf(10000.0f, -(float)i * (1.0f / 16.0f));
        float tt = (j < 16) ? (float)yy : (float)xx;
        float ang = tt * fr;
        c = cosf(ang); s = sinf(ang);
    }
    fc[2 * t] = c;
    fc[2 * t + 1] = s;
}

// ---------------- assemble (cond | patch) + pos + LayerNorm ------------------
__global__ __launch_bounds__(256) void ar_assemble_ln(
    const float* __restrict__ patch, const float* __restrict__ condr,
    const float* __restrict__ pos, const float* __restrict__ g,
    const float* __restrict__ bta, float* __restrict__ h)
{
    __shared__ float buf[EMBED];
    __shared__ float red[8];
    int m = blockIdx.x, tid = threadIdx.x;
    int b = m / SEQ, s = m % SEQ;
    const float* src = (s == 0) ? (condr + (size_t)b * EMBED)
                                : (patch + ((size_t)(b * 256 + s - 1)) * EMBED);
    float lsum = 0.f;
    for (int d = tid; d < EMBED; d += 256) {
        float v = src[d] + pos[(size_t)s * EMBED + d];
        buf[d] = v; lsum += v;
    }
    float mean = block_sum(lsum, red) * (1.f / EMBED);
    float ls2 = 0.f;
    for (int d = tid; d < EMBED; d += 256) {
        float dv = buf[d] - mean; ls2 += dv * dv;
    }
    float var = block_sum(ls2, red) * (1.f / EMBED);
    float rinv = rsqrtf(var + 1e-6f);
    for (int d = tid; d < EMBED; d += 256)
        h[(size_t)m * EMBED + d] = (buf[d] - mean) * rinv * g[d] + bta[d];
}

// ---------------- RMSNorm (half output: feeds GEMM A) ------------------------
__global__ __launch_bounds__(256) void ar_rmsnorm(
    const float* __restrict__ x, const float* __restrict__ w, __half* __restrict__ out)
{
    __shared__ float buf[EMBED];
    __shared__ float red[8];
    int m = blockIdx.x, tid = threadIdx.x;
    const float* xr = x + (size_t)m * EMBED;
    float ss = 0.f;
    for (int d = tid; d < EMBED; d += 256) {
        float v = xr[d]; buf[d] = v; ss += v * v;
    }
    ss = block_sum(ss, red);
    float r = rsqrtf(ss * (1.f / EMBED) + 1e-5f);
    __half2* o2 = (__half2*)(out + (size_t)m * EMBED);
    for (int d2 = tid; d2 < EMBED / 2; d2 += 256)
        o2[d2] = __floats2half2_rn(buf[2 * d2] * r * w[2 * d2],
                                   buf[2 * d2 + 1] * r * w[2 * d2 + 1]);
}

// ---------------- host orchestration ----------------------------------------
static inline void launch_gemm(const __half* A, const __half* B, const float* bias,
                               const float* res, float* C, int M, int N, int K) {
    dim3 grid(N / BN, (M + BM - 1) / BM);
    ar_gemm_f16<0><<<grid, 128, G_SMEM>>>(A, (const __half2*)B, bias, res, C,
                                          nullptr, nullptr, M, N, K);
}

static inline void launch_gemm_silu(const __half* A, const __half* B,
                                    const float* gate, __half* outH,
                                    int M, int N, int K) {
    dim3 grid(N / BN, (M + BM - 1) / BM);
    ar_gemm_f16<1><<<grid, 128, G_SMEM>>>(A, (const __half2*)B, nullptr, nullptr,
                                          nullptr, gate, outH, M, N, K);
}

static inline void launch_b2h(const float* in, __half* out, int K, int N, int L) {
    int total = (K / 2) * (N / 4);
    ar_b2h<<<dim3((total + 255) / 256, 1, L), 256>>>(in, (__half2*)out, K, N);
}

static inline void launch_f2h(const float* in, __half* out, size_t n) {
    size_t n4 = n / 4;
    ar_f2h<<<(unsigned)((n4 + 255) / 256), 256>>>(in, (__half2*)out, n4);
}

extern "C" void kernel_launch(void* const* d_in, const int* in_sizes, int n_in,
                              void* d_out, int out_size)
{
    const float* x       = (const float*)d_in[0];
    const float* cond    = (const float*)d_in[1];
    const float* patch_w = (const float*)d_in[2];
    const float* patch_b = (const float*)d_in[3];
    const float* ln_g    = (const float*)d_in[4];
    const float* ln_b    = (const float*)d_in[5];
    const float* pos     = (const float*)d_in[6];
    const float* cond_w  = (const float*)d_in[7];
    const float* cond_b  = (const float*)d_in[8];
    const float* wqkv    = (const float*)d_in[9];
    const float* wo      = (const float*)d_in[10];
    const float* w1      = (const float*)d_in[11];
    const float* w2      = (const float*)d_in[12];
    const float* w3      = (const float*)d_in[13];
    const float* anw     = (const float*)d_in[14];
    const float* fnw     = (const float*)d_in[15];
    float* h = (float*)d_out;

    __half *pa, *po, *pu, *pxh, *pch, *pwt;
    float *pqkv, *pf1, *pfc;
    cudaGetSymbolAddress((void**)&pa,   g_a);
    cudaGetSymbolAddress((void**)&po,   g_o);
    cudaGetSymbolAddress((void**)&pu,   g_u);
    cudaGetSymbolAddress((void**)&pxh,  g_xh);
    cudaGetSymbolAddress((void**)&pch,  g_ch);
    cudaGetSymbolAddress((void**)&pwt,  g_wt);
    cudaGetSymbolAddress((void**)&pqkv, g_qkv);
    cudaGetSymbolAddress((void**)&pf1,  g_f1);
    cudaGetSymbolAddress((void**)&pfc,  g_fc);

    cudaFuncSetAttribute(ar_gemm_f16<0>, cudaFuncAttributeMaxDynamicSharedMemorySize,
                         G_SMEM);
    cudaFuncSetAttribute(ar_gemm_f16<1>, cudaFuncAttributeMaxDynamicSharedMemorySize,
                         G_SMEM);
    cudaFuncSetAttribute(ar_fattn, cudaFuncAttributeMaxDynamicSharedMemorySize,
                         ATT_SMEM);

    __half* qkvH   = pwt + OFF_QKV;
    __half* woH    = pwt + OFF_WO;
    __half* w1H    = pwt + OFF_W1;
    __half* w3H    = pwt + OFF_W3;
    __half* w2H    = pwt + OFF_W2;
    __half* patchH = pwt + OFF_PATCH;
    __half* condH  = pwt + OFF_COND;

    // convert weights (k-pair interleaved) + A-side raw inputs to half
    launch_b2h(wqkv,    qkvH,   1024, 3072, NB);
    launch_b2h(wo,      woH,    1024, 1024, NB);
    launch_b2h(w1,      w1H,    1024, HIDDEN, NB);
    launch_b2h(w3,      w3H,    1024, HIDDEN, NB);
    launch_b2h(w2,      w2H,    HIDDEN, 1024, NB);
    launch_b2h(patch_w, patchH, 768, 1024, 1);
    launch_b2h(cond_w,  condH,  1024, 1024, 1);
    launch_f2h(x,    pxh, (size_t)8192 * 768);
    launch_f2h(cond, pch, (size_t)32 * 1024);

    // rope table
    ar_freqs<<<(SEQ * 32 + 255) / 256, 256>>>(pfc);
    // patch embed -> g_f1 (f32) ; cond embed -> g_qkv (f32, temp)
    launch_gemm(pxh, patchH, patch_b, nullptr, pf1, BATCH * 256, EMBED, 768);
    launch_gemm(pch, condH, cond_b, nullptr, pqkv, BATCH, EMBED, EMBED);
    // assemble + pos + layernorm -> h (d_out)
    ar_assemble_ln<<<MROWS, 256>>>(pf1, pqkv, pos, ln_g, ln_b, h);

    for (int l = 0; l < NB; l++) {
        __half* qkv_l = qkvH + (size_t)l * 1024 * 3072;
        __half* wo_l  = woH  + (size_t)l * 1024 * 1024;
        __half* w1_l  = w1H  + (size_t)l * 1024 * HIDDEN;
        __half* w3_l  = w3H  + (size_t)l * 1024 * HIDDEN;
        __half* w2_l  = w2H  + (size_t)l * HIDDEN * 1024;

        ar_rmsnorm<<<MROWS, 256>>>(h, anw + (size_t)l * EMBED, pa);
        launch_gemm(pa, qkv_l, nullptr, nullptr, pqkv, MROWS, 3 * EMBED, EMBED);
        ar_fattn<<<dim3(HEADS, BATCH), 128, ATT_SMEM>>>(pqkv, pfc, po);
        launch_gemm(po, wo_l, nullptr, h, h, MROWS, EMBED, EMBED);

        ar_rmsnorm<<<MROWS, 256>>>(h, fnw + (size_t)l * EMBED, pa);
        launch_gemm(pa, w1_l, nullptr, nullptr, pf1, MROWS, HIDDEN, EMBED);
        launch_gemm_silu(pa, w3_l, pf1, pu, MROWS, HIDDEN, EMBED);
        launch_gemm(pu, w2_l, nullptr, h, h, MROWS, EMBED, HIDDEN);
    }
}

// round 14
// speedup vs baseline: 1.0795x; 1.0795x over previous
#include <cuda_runtime.h>
#include <cuda_fp16.h>
#include <math.h>
#include <stdint.h>

#define EMBED   1024
#define HEADS   16
#define HD      64
#define NB      12
#define SEQ     257
#define BATCH   32
#define MROWS   (BATCH*SEQ)      // 8224
#define HIDDEN  2816

// ---------------- scratch (device globals; no allocations allowed) ----------
__device__ __align__(256) __half g_a[MROWS*EMBED];      // rmsnorm out (half, GEMM A)
__device__ __align__(256) __half g_o[MROWS*EMBED];      // attn out (half, GEMM A)
__device__ __align__(256) __half g_u[MROWS*HIDDEN];     // silu(u)*v (half, GEMM A)
__device__ __align__(256) __half g_xh[8192*768];        // x (half)
__device__ __align__(256) __half g_ch[32*1024];         // cond (half)
__device__ __align__(256) float  g_qkv[MROWS*3*EMBED];  // cond-out f32 / half qkv (roped)
__device__ __align__(256) float  g_f1[MROWS*HIDDEN];    // patch-out f32 / half gate
__device__ __align__(256) float  g_fc[SEQ*32*2];        // rope cos/sin table

// half weights, k-pair interleaved: [K/2][N] half2
#define OFF_QKV   ((size_t)0)
#define OFF_WO    (OFF_QKV + (size_t)NB*1024*3072)
#define OFF_W1    (OFF_WO  + (size_t)NB*1024*1024)
#define OFF_W3    (OFF_W1  + (size_t)NB*1024*HIDDEN)
#define OFF_W2    (OFF_W3  + (size_t)NB*1024*HIDDEN)
#define OFF_PATCH (OFF_W2  + (size_t)NB*HIDDEN*1024)
#define OFF_COND  (OFF_PATCH + (size_t)768*1024)
#define WT_TOTAL  (OFF_COND + (size_t)1024*1024)
__device__ __align__(256) __half g_wt[WT_TOTAL];

// attention warp->q-tile schedule (chunk-balanced 38/38/39/38)
__constant__ int g_wtiles[20] = {16,12,5,1,-1, 15,13,4,2,-1, 14,11,6,3,0, 10,9,8,7,-1};

// ---------------- helpers ----------------------------------------------------
__device__ __forceinline__ uint32_t smem_u32(const void* p) {
    uint32_t a;
    asm("{ .reg .u64 t; cvta.to.shared.u64 t, %1; cvt.u32.u64 %0, t; }" : "=r"(a) : "l"(p));
    return a;
}

__device__ __forceinline__ uint32_t pack_h2(float a, float b) {
    __half2 h = __floats2half2_rn(a, b);
    return *(uint32_t*)&h;
}

__device__ __forceinline__ void mma_f16(float c[4], const uint32_t a[4],
                                        const uint32_t b[2]) {
    asm volatile(
        "mma.sync.aligned.m16n8k16.row.col.f32.f16.f16.f32 "
        "{%0,%1,%2,%3}, {%4,%5,%6,%7}, {%8,%9}, {%0,%1,%2,%3};"
        : "+f"(c[0]), "+f"(c[1]), "+f"(c[2]), "+f"(c[3])
        : "r"(a[0]), "r"(a[1]), "r"(a[2]), "r"(a[3]), "r"(b[0]), "r"(b[1]));
}

__device__ __forceinline__ void cp16(uint32_t dst, const void* src, int sz) {
    asm volatile("cp.async.cg.shared.global [%0], [%1], 16, %2;"
        :: "r"(dst), "l"(src), "r"(sz) : "memory");
}

// ---------------- pipelined FP16 tensor-core GEMM ----------------------------
// Template-specialized epilogues (compile-time, separate instantiations):
//   EPI=0: C(f32) = acc (+bias) (+res)                     [proven hot path]
//   EPI=1: outH(half) = silu(gateH) * acc                  [w3 GEMM]
//   EPI=2: outH(half) = rope(acc) for cols<2048, else acc  [qkv GEMM]
//   EPI=3: outH(half) = acc                                [w1 GEMM]
#define BM     128
#define BN     128
#define BK     64
#define A_SW   36
#define B_SW   136
#define A_WORDS (BM*A_SW)
#define B_WORDS ((BK/2)*B_SW)
#define ST_WORDS (A_WORDS+B_WORDS)
#define G_SMEM (3*ST_WORDS*4)

template<int EPI>
__global__ __launch_bounds__(128) void ar_gemm_f16(
    const __half* __restrict__ A, const __half2* __restrict__ B2,
    const float* __restrict__ bias, const float* __restrict__ res,
    float* __restrict__ C, const __half* __restrict__ gateH,
    __half* __restrict__ outH, const float* __restrict__ fc,
    int M, int N, int K)
{
    extern __shared__ uint32_t sm[];
    uint32_t sm_u = smem_u32(sm);

    int tid = threadIdx.x, lane = tid & 31, warp = tid >> 5;
    int wm = warp & 1, wn = warp >> 1;
    int bm = blockIdx.y * BM, bn = blockIdx.x * BN;
    int g = lane >> 2, tg = lane & 3;

    float acc[4][8][4];
    #pragma unroll
    for (int i = 0; i < 4; i++)
        #pragma unroll
        for (int j = 0; j < 8; j++)
            #pragma unroll
            for (int t = 0; t < 4; t++) acc[i][j][t] = 0.f;

    const int NC = K / BK;

    auto load_chunk = [&](int cidx) {
        int s = cidx % 3;
        int k0 = cidx * BK;
        uint32_t st = sm_u + (uint32_t)(s * ST_WORDS) * 4u;
        #pragma unroll
        for (int i = 0; i < 8; i++) {
            int idx = tid + (i << 7);
            int r = idx >> 3, cc = idx & 7;
            uint32_t dst = st + (uint32_t)(r * A_SW + cc * 4) * 4u;
            int gm = bm + r;
            bool v = (gm < M);
            const __half* src = A + (size_t)(v ? gm : 0) * K + k0 + cc * 8;
            cp16(dst, src, v ? 16 : 0);
        }
        #pragma unroll
        for (int i = 0; i < 8; i++) {
            int idx = tid + (i << 7);
            int r = idx >> 5, cc = idx & 31;
            uint32_t dst = st + (uint32_t)(A_WORDS + r * B_SW + cc * 4) * 4u;
            const __half2* src = B2 + (size_t)(k0 / 2 + r) * N + bn + cc * 4;
            cp16(dst, src, 16);
        }
    };

    auto compute = [&](int s) {
        const uint32_t* St = sm + s * ST_WORDS;
        const uint32_t* Ab = St;
        const uint32_t* Bb = St + A_WORDS;
        int m0 = wm * 64 + g;
        int n0 = wn * 64 + g;
        #pragma unroll
        for (int ks = 0; ks < 4; ks++) {
            int kw = ks * 8;
            uint32_t af[4][4];
            #pragma unroll
            for (int mt = 0; mt < 4; mt++) {
                int base = (m0 + mt * 16) * A_SW + kw + tg;
                af[mt][0] = Ab[base];
                af[mt][1] = Ab[base + 8 * A_SW];
                af[mt][2] = Ab[base + 4];
                af[mt][3] = Ab[base + 8 * A_SW + 4];
            }
            uint32_t bf[8][2];
            #pragma unroll
            for (int nt = 0; nt < 8; nt++) {
                int bb = (kw + tg) * B_SW + n0 + nt * 8;
                bf[nt][0] = Bb[bb];
                bf[nt][1] = Bb[bb + 4 * B_SW];
            }
            #pragma unroll
            for (int mt = 0; mt < 4; mt++)
                #pragma unroll
                for (int nt = 0; nt < 8; nt++)
                    mma_f16(acc[mt][nt], af[mt], bf[nt]);
        }
    };

    load_chunk(0);
    asm volatile("cp.async.commit_group;" ::: "memory");
    load_chunk(1);
    asm volatile("cp.async.commit_group;" ::: "memory");
    load_chunk(2);
    asm volatile("cp.async.commit_group;" ::: "memory");

    for (int c = 0; c < NC; c++) {
        asm volatile("cp.async.wait_group 2;" ::: "memory");
        __syncthreads();
        compute(c % 3);
        __syncthreads();
        if (c + 3 < NC) load_chunk(c + 3);
        asm volatile("cp.async.commit_group;" ::: "memory");
    }

    #pragma unroll
    for (int mt = 0; mt < 4; mt++) {
        int rbase = bm + wm * 64 + mt * 16 + g;
        #pragma unroll
        for (int half = 0; half < 2; half++) {
            int r = rbase + half * 8;
            if (r >= M) continue;
            int spos = (EPI == 2) ? (r % SEQ) : 0;
            #pragma unroll
            for (int nt = 0; nt < 8; nt++) {
                int cl = bn + wn * 64 + nt * 8 + 2 * tg;
                float2 v;
                v.x = acc[mt][nt][half * 2 + 0];
                v.y = acc[mt][nt][half * 2 + 1];
                if (EPI == 0) {
                    if (bias) { v.x += bias[cl]; v.y += bias[cl + 1]; }
                    if (res) {
                        float2 rr = *(const float2*)(res + (size_t)r * N + cl);
                        v.x += rr.x; v.y += rr.y;
                    }
                    *(float2*)(C + (size_t)r * N + cl) = v;
                } else if (EPI == 1) {
                    __half2 gh = *(const __half2*)(gateH + (size_t)r * N + cl);
                    float2 gg = __half22float2(gh);
                    float s0 = gg.x / (1.f + __expf(-gg.x)) * v.x;
                    float s1 = gg.y / (1.f + __expf(-gg.y)) * v.y;
                    *(__half2*)(outH + (size_t)r * N + cl) = __floats2half2_rn(s0, s1);
                } else if (EPI == 2) {
                    if (cl < 2048) {                  // rope on q,k pairs
                        int jj = (cl & 63) >> 1;
                        float cc = fc[(spos * 32 + jj) * 2];
                        float sn = fc[(spos * 32 + jj) * 2 + 1];
                        float x0 = v.x, x1 = v.y;
                        v.x = x0 * cc - x1 * sn;
                        v.y = x1 * cc + x0 * sn;
                    }
                    *(__half2*)(outH + (size_t)r * N + cl) = __floats2half2_rn(v.x, v.y);
                } else {                               // EPI == 3
                    *(__half2*)(outH + (size_t)r * N + cl) = __floats2half2_rn(v.x, v.y);
                }
            }
        }
    }
}

// ---------------- tensor-core flash attention (half qkv input, pre-roped) ----
// R12-proven structure: K via cp.async (rows contiguous 128B), V transposed,
// Q fragments direct half2 loads scaled by exact 0.125.
#define KH_WORDS (264*36)
#define VT_WORDS (64*140)
#define ATT_SMEM ((KH_WORDS+VT_WORDS)*4)

__global__ __launch_bounds__(128) void ar_fattn(const __half* __restrict__ qkv,
                                                __half* __restrict__ o)
{
    extern __shared__ uint32_t smw[];
    uint32_t* KhW = smw;
    uint32_t* VtW = smw + KH_WORDS;
    int h = blockIdx.x, b = blockIdx.y;
    int tid = threadIdx.x, lane = tid & 31, warp = tid >> 5;
    int g = lane >> 2, tg = lane & 3;
    uint32_t kh_u = smem_u32(KhW);

    #pragma unroll 8
    for (int i = tid; i < KH_WORDS + VT_WORDS; i += 128) smw[i] = 0;
    __syncthreads();

    const __half* kbase = qkv + (size_t)b * SEQ * 3072 + 1024 + h * 64;
    #pragma unroll 4
    for (int idx = tid; idx < 257 * 8; idx += 128) {      // K: cp.async 16B each
        int s_ = idx >> 3, cb = idx & 7;
        cp16(kh_u + (uint32_t)(s_ * 36 + 4 * cb) * 4u,
             kbase + (size_t)s_ * 3072 + cb * 8, 16);
    }
    asm volatile("cp.async.commit_group;" ::: "memory");
    const __half* vbase = kbase + 1024;
    {
        int d = tid & 63;
        #pragma unroll 4
        for (int jp = tid >> 6; jp < 129; jp += 2) {
            int j0 = 2 * jp, j1 = j0 + 1;
            uint32_t w = (uint32_t)*(const uint16_t*)(vbase + (size_t)j0 * 3072 + d);
            if (j1 < 257)
                w |= (uint32_t)*(const uint16_t*)(vbase + (size_t)j1 * 3072 + d) << 16;
            VtW[d * 140 + jp] = w;
        }
    }
    asm volatile("cp.async.wait_group 0;" ::: "memory");
    __syncthreads();

    const __half2 scale = __float2half2_rn(0.125f);

    for (int ti = 0; ti < 5; ti++) {
        int t = g_wtiles[warp * 5 + ti];
        if (t < 0) break;
        int q0 = t * 16;

        uint32_t aq[4][4];
        int r0c = min(q0 + g, 256), r1c = min(q0 + g + 8, 256);
        const __half* q0p = qkv + (size_t)(b * SEQ + r0c) * 3072 + h * 64;
        const __half* q1p = qkv + (size_t)(b * SEQ + r1c) * 3072 + h * 64;
        #pragma unroll
        for (int s = 0; s < 4; s++) {
            int dlo = s * 16 + 2 * tg, dhi = dlo + 8;
            __half2 hv;
            hv = __hmul2(*(const __half2*)(q0p + dlo), scale); aq[s][0] = *(uint32_t*)&hv;
            hv = __hmul2(*(const __half2*)(q1p + dlo), scale); aq[s][1] = *(uint32_t*)&hv;
            hv = __hmul2(*(const __half2*)(q0p + dhi), scale); aq[s][2] = *(uint32_t*)&hv;
            hv = __hmul2(*(const __half2*)(q1p + dhi), scale); aq[s][3] = *(uint32_t*)&hv;
        }

        float m0 = -1e30f, m1 = -1e30f, l0 = 0.f, l1 = 0.f;
        float acc[8][4];
        #pragma unroll
        for (int nt = 0; nt < 8; nt++)
            #pragma unroll
            for (int q = 0; q < 4; q++) acc[nt][q] = 0.f;

        int row0 = q0 + g, row1 = row0 + 8;
        int nchunks = t + 1;
        for (int ch = 0; ch < nchunks; ch++) {
            int j0c = ch * 16;
            float sc0[4] = {0.f, 0.f, 0.f, 0.f};
            float sc1[4] = {0.f, 0.f, 0.f, 0.f};
            #pragma unroll
            for (int s = 0; s < 4; s++) {
                uint32_t b0[2], b1[2];
                int base0 = (j0c + g) * 36 + 8 * s + tg;
                b0[0] = KhW[base0];
                b0[1] = KhW[base0 + 4];
                b1[0] = KhW[base0 + 8 * 36];
                b1[1] = KhW[base0 + 8 * 36 + 4];
                mma_f16(sc0, aq[s], b0);
                mma_f16(sc1, aq[s], b1);
            }
            if (ch == t) {
                int cb = j0c + 2 * tg;
                if (cb     > row0) sc0[0] = -1e30f;
                if (cb + 1 > row0) sc0[1] = -1e30f;
                if (cb     > row1) sc0[2] = -1e30f;
                if (cb + 1 > row1) sc0[3] = -1e30f;
                if (cb + 8 > row0) sc1[0] = -1e30f;
                if (cb + 9 > row0) sc1[1] = -1e30f;
                if (cb + 8 > row1) sc1[2] = -1e30f;
                if (cb + 9 > row1) sc1[3] = -1e30f;
            }
            float cm0 = fmaxf(fmaxf(sc0[0], sc0[1]), fmaxf(sc1[0], sc1[1]));
            float cm1 = fmaxf(fmaxf(sc0[2], sc0[3]), fmaxf(sc1[2], sc1[3]));
            cm0 = fmaxf(cm0, __shfl_xor_sync(0xffffffffu, cm0, 1));
            cm0 = fmaxf(cm0, __shfl_xor_sync(0xffffffffu, cm0, 2));
            cm1 = fmaxf(cm1, __shfl_xor_sync(0xffffffffu, cm1, 1));
            cm1 = fmaxf(cm1, __shfl_xor_sync(0xffffffffu, cm1, 2));
            float nm0 = fmaxf(m0, cm0), nm1 = fmaxf(m1, cm1);
            float corr0 = __expf(m0 - nm0), corr1 = __expf(m1 - nm1);
            float p00 = __expf(sc0[0] - nm0), p01 = __expf(sc0[1] - nm0);
            float p02 = __expf(sc0[2] - nm1), p03 = __expf(sc0[3] - nm1);
            float p10 = __expf(sc1[0] - nm0), p11 = __expf(sc1[1] - nm0);
            float p12 = __expf(sc1[2] - nm1), p13 = __expf(sc1[3] - nm1);
            float ps0 = (p00 + p01) + (p10 + p11);
            float ps1 = (p02 + p03) + (p12 + p13);
            ps0 += __shfl_xor_sync(0xffffffffu, ps0, 1);
            ps0 += __shfl_xor_sync(0xffffffffu, ps0, 2);
            ps1 += __shfl_xor_sync(0xffffffffu, ps1, 1);
            ps1 += __shfl_xor_sync(0xffffffffu, ps1, 2);
            l0 = l0 * corr0 + ps0;
            l1 = l1 * corr1 + ps1;
            m0 = nm0; m1 = nm1;

            uint32_t ap[4];
            ap[0] = pack_h2(p00, p01);
            ap[1] = pack_h2(p02, p03);
            ap[2] = pack_h2(p10, p11);
            ap[3] = pack_h2(p12, p13);

            int jh = (j0c >> 1) + tg;
            #pragma unroll
            for (int nt = 0; nt < 8; nt++) {
                acc[nt][0] *= corr0; acc[nt][1] *= corr0;
                acc[nt][2] *= corr1; acc[nt][3] *= corr1;
                uint32_t bv[2];
                int vb = (nt * 8 + g) * 140 + jh;
                bv[0] = VtW[vb];
                bv[1] = VtW[vb + 4];
                mma_f16(acc[nt], ap, bv);
            }
        }

        float inv0 = 1.f / l0, inv1 = 1.f / l1;
        __half* ob = o + (size_t)b * SEQ * EMBED + h * 64 + 2 * tg;
        if (row0 < SEQ) {
            __half* orow = ob + (size_t)row0 * EMBED;
            #pragma unroll
            for (int nt = 0; nt < 8; nt++)
                *(__half2*)(orow + nt * 8) =
                    __floats2half2_rn(acc[nt][0] * inv0, acc[nt][1] * inv0);
        }
        if (row1 < SEQ) {
            __half* orow = ob + (size_t)row1 * EMBED;
            #pragma unroll
            for (int nt = 0; nt < 8; nt++)
                *(__half2*)(orow + nt * 8) =
                    __floats2half2_rn(acc[nt][2] * inv1, acc[nt][3] * inv1);
        }
    }
}

// ---------------- weight convert: [K][N] f32 -> [K/2][N] half2 (wide) --------
__global__ __launch_bounds__(256) void ar_b2h(const float* __restrict__ in,
                                              __half2* __restrict__ out,
                                              int K, int N) {
    size_t z = blockIdx.z;
    in  += z * (size_t)K * N;
    out += z * (size_t)(K / 2) * N;
    int total = (K / 2) * (N / 4);
    int idx = blockIdx.x * blockDim.x + threadIdx.x;
    if (idx >= total) return;
    int nq = N / 4;
    int k2 = idx / nq, n4 = (idx - k2 * nq) * 4;
    float4 lo = *(const float4*)(in + (size_t)(2 * k2) * N + n4);
    float4 hi = *(const float4*)(in + (size_t)(2 * k2 + 1) * N + n4);
    __half2* op = out + (size_t)k2 * N + n4;
    op[0] = __floats2half2_rn(lo.x, hi.x);
    op[1] = __floats2half2_rn(lo.y, hi.y);
    op[2] = __floats2half2_rn(lo.z, hi.z);
    op[3] = __floats2half2_rn(lo.w, hi.w);
}

// ---------------- activation convert: f32 -> f16 flat ------------------------
__global__ void ar_f2h(const float* __restrict__ in, __half2* __restrict__ out,
                       size_t n4) {
    size_t i = (size_t)blockIdx.x * blockDim.x + threadIdx.x;
    if (i < n4) {
        float4 v = ((const float4*)in)[i];
        out[2 * i]     = __floats2half2_rn(v.x, v.y);
        out[2 * i + 1] = __floats2half2_rn(v.z, v.w);
    }
}

// ---------------- reductions ------------------------------------------------
__device__ __forceinline__ float block_sum(float v, float* red) {
    int tid = threadIdx.x;
    #pragma unroll
    for (int o = 16; o > 0; o >>= 1) v += __shfl_xor_sync(0xffffffffu, v, o);
    if ((tid & 31) == 0) red[tid >> 5] = v;
    __syncthreads();
    if (tid == 0) {
        float s = red[0];
        int nw = blockDim.x >> 5;
        for (int i = 1; i < nw; i++) s += red[i];
        red[0] = s;
    }
    __syncthreads();
    float r = red[0];
    __syncthreads();
    return r;
}

// ---------------- rope frequency table --------------------------------------
__global__ void ar_freqs(float* __restrict__ fc) {
    int t = blockIdx.x * blockDim.x + threadIdx.x;
    if (t >= SEQ * 32) return;
    int p = t >> 5, j = t & 31;
    float c = 0.f, s = 0.f;
    if (p > 0) {                       // cls token keeps cos=sin=0 (ref!)
        int pp = p - 1, yy = pp >> 4, xx = pp & 15;
        int i = j & 15;
        float fr = powf(10000.0f, -(float)i * (1.0f / 16.0f));
        float tt = (j < 16) ? (float)yy : (float)xx;
        float ang = tt * fr;
        c = cosf(ang); s = sinf(ang);
    }
    fc[2 * t] = c;
    fc[2 * t + 1] = s;
}

// ---------------- assemble (cond | patch) + pos + LayerNorm ------------------
__global__ __launch_bounds__(256) void ar_assemble_ln(
    const float* __restrict__ patch, const float* __restrict__ condr,
    const float* __restrict__ pos, const float* __restrict__ g,
    const float* __restrict__ bta, float* __restrict__ h)
{
    __shared__ float buf[EMBED];
    __shared__ float red[8];
    int m = blockIdx.x, tid = threadIdx.x;
    int b = m / SEQ, s = m % SEQ;
    const float* src = (s == 0) ? (condr + (size_t)b * EMBED)
                                : (patch + ((size_t)(b * 256 + s - 1)) * EMBED);
    float lsum = 0.f;
    for (int d = tid; d < EMBED; d += 256) {
        float v = src[d] + pos[(size_t)s * EMBED + d];
        buf[d] = v; lsum += v;
    }
    float mean = block_sum(lsum, red) * (1.f / EMBED);
    float ls2 = 0.f;
    for (int d = tid; d < EMBED; d += 256) {
        float dv = buf[d] - mean; ls2 += dv * dv;
    }
    float var = block_sum(ls2, red) * (1.f / EMBED);
    float rinv = rsqrtf(var + 1e-6f);
    for (int d = tid; d < EMBED; d += 256)
        h[(size_t)m * EMBED + d] = (buf[d] - mean) * rinv * g[d] + bta[d];
}

// ---------------- RMSNorm (half output: feeds GEMM A) ------------------------
__global__ __launch_bounds__(256) void ar_rmsnorm(
    const float* __restrict__ x, const float* __restrict__ w, __half* __restrict__ out)
{
    __shared__ float buf[EMBED];
    __shared__ float red[8];
    int m = blockIdx.x, tid = threadIdx.x;
    const float* xr = x + (size_t)m * EMBED;
    float ss = 0.f;
    for (int d = tid; d < EMBED; d += 256) {
        float v = xr[d]; buf[d] = v; ss += v * v;
    }
    ss = block_sum(ss, red);
    float r = rsqrtf(ss * (1.f / EMBED) + 1e-5f);
    __half2* o2 = (__half2*)(out + (size_t)m * EMBED);
    for (int d2 = tid; d2 < EMBED / 2; d2 += 256)
        o2[d2] = __floats2half2_rn(buf[2 * d2] * r * w[2 * d2],
                                   buf[2 * d2 + 1] * r * w[2 * d2 + 1]);
}

// ---------------- host orchestration ----------------------------------------
static inline void launch_gemm(const __half* A, const __half* B, const float* bias,
                               const float* res, float* C, int M, int N, int K) {
    dim3 grid(N / BN, (M + BM - 1) / BM);
    ar_gemm_f16<0><<<grid, 128, G_SMEM>>>(A, (const __half2*)B, bias, res, C,
                                          nullptr, nullptr, nullptr, M, N, K);
}

static inline void launch_gemm_silu(const __half* A, const __half* B,
                                    const __half* gateH, __half* outH,
                                    int M, int N, int K) {
    dim3 grid(N / BN, (M + BM - 1) / BM);
    ar_gemm_f16<1><<<grid, 128, G_SMEM>>>(A, (const __half2*)B, nullptr, nullptr,
                                          nullptr, gateH, outH, nullptr, M, N, K);
}

static inline void launch_gemm_rope(const __half* A, const __half* B,
                                    __half* outH, const float* fc,
                                    int M, int N, int K) {
    dim3 grid(N / BN, (M + BM - 1) / BM);
    ar_gemm_f16<2><<<grid, 128, G_SMEM>>>(A, (const __half2*)B, nullptr, nullptr,
                                          nullptr, nullptr, outH, fc, M, N, K);
}

static inline void launch_gemm_h(const __half* A, const __half* B,
                                 __half* outH, int M, int N, int K) {
    dim3 grid(N / BN, (M + BM - 1) / BM);
    ar_gemm_f16<3><<<grid, 128, G_SMEM>>>(A, (const __half2*)B, nullptr, nullptr,
                                          nullptr, nullptr, outH, nullptr, M, N, K);
}

static inline void launch_b2h(const float* in, __half* out, int K, int N, int L) {
    int total = (K / 2) * (N / 4);
    ar_b2h<<<dim3((total + 255) / 256, 1, L), 256>>>(in, (__half2*)out, K, N);
}

static inline void launch_f2h(const float* in, __half* out, size_t n) {
    size_t n4 = n / 4;
    ar_f2h<<<(unsigned)((n4 + 255) / 256), 256>>>(in, (__half2*)out, n4);
}

extern "C" void kernel_launch(void* const* d_in, const int* in_sizes, int n_in,
                              void* d_out, int out_size)
{
    const float* x       = (const float*)d_in[0];
    const float* cond    = (const float*)d_in[1];
    const float* patch_w = (const float*)d_in[2];
    const float* patch_b = (const float*)d_in[3];
    const float* ln_g    = (const float*)d_in[4];
    const float* ln_b    = (const float*)d_in[5];
    const float* pos     = (const float*)d_in[6];
    const float* cond_w  = (const float*)d_in[7];
    const float* cond_b  = (const float*)d_in[8];
    const float* wqkv    = (const float*)d_in[9];
    const float* wo      = (const float*)d_in[10];
    const float* w1      = (const float*)d_in[11];
    const float* w2      = (const float*)d_in[12];
    const float* w3      = (const float*)d_in[13];
    const float* anw     = (const float*)d_in[14];
    const float* fnw     = (const float*)d_in[15];
    float* h = (float*)d_out;

    __half *pa, *po, *pu, *pxh, *pch, *pwt;
    float *pqkv, *pf1, *pfc;
    cudaGetSymbolAddress((void**)&pa,   g_a);
    cudaGetSymbolAddress((void**)&po,   g_o);
    cudaGetSymbolAddress((void**)&pu,   g_u);
    cudaGetSymbolAddress((void**)&pxh,  g_xh);
    cudaGetSymbolAddress((void**)&pch,  g_ch);
    cudaGetSymbolAddress((void**)&pwt,  g_wt);
    cudaGetSymbolAddress((void**)&pqkv, g_qkv);
    cudaGetSymbolAddress((void**)&pf1,  g_f1);
    cudaGetSymbolAddress((void**)&pfc,  g_fc);

    __half* pqh = (__half*)pqkv;    // half view: roped qkv
    __half* pgh = (__half*)pf1;     // half view: w1 gate

    cudaFuncSetAttribute(ar_gemm_f16<0>, cudaFuncAttributeMaxDynamicSharedMemorySize,
                         G_SMEM);
    cudaFuncSetAttribute(ar_gemm_f16<1>, cudaFuncAttributeMaxDynamicSharedMemorySize,
                         G_SMEM);
    cudaFuncSetAttribute(ar_gemm_f16<2>, cudaFuncAttributeMaxDynamicSharedMemorySize,
                         G_SMEM);
    cudaFuncSetAttribute(ar_gemm_f16<3>, cudaFuncAttributeMaxDynamicSharedMemorySize,
                         G_SMEM);
    cudaFuncSetAttribute(ar_fattn, cudaFuncAttributeMaxDynamicSharedMemorySize,
                         ATT_SMEM);

    __half* qkvH   = pwt + OFF_QKV;
    __half* woH    = pwt + OFF_WO;
    __half* w1H    = pwt + OFF_W1;
    __half* w3H    = pwt + OFF_W3;
    __half* w2H    = pwt + OFF_W2;
    __half* patchH = pwt + OFF_PATCH;
    __half* condH  = pwt + OFF_COND;

    // convert weights (k-pair interleaved) + A-side raw inputs to half
    launch_b2h(wqkv,    qkvH,   1024, 3072, NB);
    launch_b2h(wo,      woH,    1024, 1024, NB);
    launch_b2h(w1,      w1H,    1024, HIDDEN, NB);
    launch_b2h(w3,      w3H,    1024, HIDDEN, NB);
    launch_b2h(w2,      w2H,    HIDDEN, 1024, NB);
    launch_b2h(patch_w, patchH, 768, 1024, 1);
    launch_b2h(cond_w,  condH,  1024, 1024, 1);
    launch_f2h(x,    pxh, (size_t)8192 * 768);
    launch_f2h(cond, pch, (size_t)32 * 1024);

    // rope table
    ar_freqs<<<(SEQ * 32 + 255) / 256, 256>>>(pfc);
    // patch embed -> g_f1 (f32) ; cond embed -> g_qkv (f32, temp)
    launch_gemm(pxh, patchH, patch_b, nullptr, pf1, BATCH * 256, EMBED, 768);
    launch_gemm(pch, condH, cond_b, nullptr, pqkv, BATCH, EMBED, EMBED);
    // assemble + pos + layernorm -> h (d_out)
    ar_assemble_ln<<<MROWS, 256>>>(pf1, pqkv, pos, ln_g, ln_b, h);

    for (int l = 0; l < NB; l++) {
        __half* qkv_l = qkvH + (size_t)l * 1024 * 3072;
        __half* wo_l  = woH  + (size_t)l * 1024 * 1024;
        __half* w1_l  = w1H  + (size_t)l * 1024 * HIDDEN;
        __half* w3_l  = w3H  + (size_t)l * 1024 * HIDDEN;
        __half* w2_l  = w2H  + (size_t)l * HIDDEN * 1024;

        ar_rmsnorm<<<MROWS, 256>>>(h, anw + (size_t)l * EMBED, pa);
        // qkv GEMM with fused rope, half output
        launch_gemm_rope(pa, qkv_l, pqh, pfc, MROWS, 3 * EMBED, EMBED);
        ar_fattn<<<dim3(HEADS, BATCH), 128, ATT_SMEM>>>(pqh, po);
        launch_gemm(po, wo_l, nullptr, h, h, MROWS, EMBED, EMBED);

        ar_rmsnorm<<<MROWS, 256>>>(h, fnw + (size_t)l * EMBED, pa);
        // w1 GEMM -> half gate
        launch_gemm_h(pa, w1_l, pgh, MROWS, HIDDEN, EMBED);
        // w3 GEMM with fused silu(gate)*acc -> half u
        launch_gemm_silu(pa, w3_l, pgh, pu, MROWS, HIDDEN, EMBED);
        launch_gemm(pu, w2_l, nullptr, h, h, MROWS, EMBED, HIDDEN);
    }
}

// round 15
// speedup vs baseline: 1.1094x; 1.0277x over previous
#include <cuda_runtime.h>
#include <cuda_fp16.h>
#include <math.h>
#include <stdint.h>

#define EMBED   1024
#define HEADS   16
#define HD      64
#define NB      12
#define SEQ     257
#define BATCH   32
#define MROWS   (BATCH*SEQ)      // 8224
#define HIDDEN  2816

// ---------------- scratch (device globals; no allocations allowed) ----------
__device__ __align__(256) __half g_a[MROWS*EMBED];      // rmsnorm out (half, GEMM A)
__device__ __align__(256) __half g_o[MROWS*EMBED];      // attn out (half, GEMM A)
__device__ __align__(256) __half g_u[MROWS*HIDDEN];     // silu(u)*v (half, GEMM A)
__device__ __align__(256) __half g_xh[8192*768];        // x (half)
__device__ __align__(256) __half g_ch[32*1024];         // cond (half)
__device__ __align__(256) float  g_qkv[MROWS*3*EMBED];  // cond-out f32 / half qkv (roped)
__device__ __align__(256) float  g_f1[MROWS*HIDDEN];    // patch-out f32 / half gate
__device__ __align__(256) float  g_fc[SEQ*32*2];        // rope cos/sin table

// half weights, k-pair interleaved: [K/2][N] half2
#define OFF_QKV   ((size_t)0)
#define OFF_WO    (OFF_QKV + (size_t)NB*1024*3072)
#define OFF_W1    (OFF_WO  + (size_t)NB*1024*1024)
#define OFF_W3    (OFF_W1  + (size_t)NB*1024*HIDDEN)
#define OFF_W2    (OFF_W3  + (size_t)NB*1024*HIDDEN)
#define OFF_PATCH (OFF_W2  + (size_t)NB*HIDDEN*1024)
#define OFF_COND  (OFF_PATCH + (size_t)768*1024)
#define WT_TOTAL  (OFF_COND + (size_t)1024*1024)
__device__ __align__(256) __half g_wt[WT_TOTAL];

// attention warp->q-tile schedule (chunk-balanced 38/38/39/38)
__constant__ int g_wtiles[20] = {16,12,5,1,-1, 15,13,4,2,-1, 14,11,6,3,0, 10,9,8,7,-1};

// ---------------- helpers ----------------------------------------------------
__device__ __forceinline__ uint32_t smem_u32(const void* p) {
    uint32_t a;
    asm("{ .reg .u64 t; cvta.to.shared.u64 t, %1; cvt.u32.u64 %0, t; }" : "=r"(a) : "l"(p));
    return a;
}

__device__ __forceinline__ uint32_t pack_h2(float a, float b) {
    __half2 h = __floats2half2_rn(a, b);
    return *(uint32_t*)&h;
}

__device__ __forceinline__ void mma_f16(float c[4], const uint32_t a[4],
                                        const uint32_t b[2]) {
    asm volatile(
        "mma.sync.aligned.m16n8k16.row.col.f32.f16.f16.f32 "
        "{%0,%1,%2,%3}, {%4,%5,%6,%7}, {%8,%9}, {%0,%1,%2,%3};"
        : "+f"(c[0]), "+f"(c[1]), "+f"(c[2]), "+f"(c[3])
        : "r"(a[0]), "r"(a[1]), "r"(a[2]), "r"(a[3]), "r"(b[0]), "r"(b[1]));
}

__device__ __forceinline__ void cp16(uint32_t dst, const void* src, int sz) {
    asm volatile("cp.async.cg.shared.global [%0], [%1], 16, %2;"
        :: "r"(dst), "l"(src), "r"(sz) : "memory");
}

// ---------------- pipelined FP16 tensor-core GEMM ----------------------------
// Template-specialized epilogues (compile-time, separate instantiations):
//   EPI=0: C(f32) = acc (+bias) (+res)                     [proven hot path]
//   EPI=1: outH(half) = silu(gateH) * acc                  [w3 GEMM]
//   EPI=2: outH(half) = rope(acc) for cols<2048, else acc  [qkv GEMM]
//   EPI=3: outH(half) = acc                                [w1 GEMM]
#define BM     128
#define BN     128
#define BK     64
#define A_SW   36
#define B_SW   136
#define A_WORDS (BM*A_SW)
#define B_WORDS ((BK/2)*B_SW)
#define ST_WORDS (A_WORDS+B_WORDS)
#define G_SMEM (3*ST_WORDS*4)

template<int EPI>
__global__ __launch_bounds__(128) void ar_gemm_f16(
    const __half* __restrict__ A, const __half2* __restrict__ B2,
    const float* __restrict__ bias, const float* __restrict__ res,
    float* __restrict__ C, const __half* __restrict__ gateH,
    __half* __restrict__ outH, const float* __restrict__ fc,
    int M, int N, int K)
{
    extern __shared__ uint32_t sm[];
    uint32_t sm_u = smem_u32(sm);

    int tid = threadIdx.x, lane = tid & 31, warp = tid >> 5;
    int wm = warp & 1, wn = warp >> 1;
    int bm = blockIdx.y * BM, bn = blockIdx.x * BN;
    int g = lane >> 2, tg = lane & 3;

    float acc[4][8][4];
    #pragma unroll
    for (int i = 0; i < 4; i++)
        #pragma unroll
        for (int j = 0; j < 8; j++)
            #pragma unroll
            for (int t = 0; t < 4; t++) acc[i][j][t] = 0.f;

    const int NC = K / BK;

    auto load_chunk = [&](int cidx) {
        int s = cidx % 3;
        int k0 = cidx * BK;
        uint32_t st = sm_u + (uint32_t)(s * ST_WORDS) * 4u;
        #pragma unroll
        for (int i = 0; i < 8; i++) {
            int idx = tid + (i << 7);
            int r = idx >> 3, cc = idx & 7;
            uint32_t dst = st + (uint32_t)(r * A_SW + cc * 4) * 4u;
            int gm = bm + r;
            bool v = (gm < M);
            const __half* src = A + (size_t)(v ? gm : 0) * K + k0 + cc * 8;
            cp16(dst, src, v ? 16 : 0);
        }
        #pragma unroll
        for (int i = 0; i < 8; i++) {
            int idx = tid + (i << 7);
            int r = idx >> 5, cc = idx & 31;
            uint32_t dst = st + (uint32_t)(A_WORDS + r * B_SW + cc * 4) * 4u;
            const __half2* src = B2 + (size_t)(k0 / 2 + r) * N + bn + cc * 4;
            cp16(dst, src, 16);
        }
    };

    auto compute = [&](int s) {
        const uint32_t* St = sm + s * ST_WORDS;
        const uint32_t* Ab = St;
        const uint32_t* Bb = St + A_WORDS;
        int m0 = wm * 64 + g;
        int n0 = wn * 64 + g;
        #pragma unroll
        for (int ks = 0; ks < 4; ks++) {
            int kw = ks * 8;
            uint32_t af[4][4];
            #pragma unroll
            for (int mt = 0; mt < 4; mt++) {
                int base = (m0 + mt * 16) * A_SW + kw + tg;
                af[mt][0] = Ab[base];
                af[mt][1] = Ab[base + 8 * A_SW];
                af[mt][2] = Ab[base + 4];
                af[mt][3] = Ab[base + 8 * A_SW + 4];
            }
            uint32_t bf[8][2];
            #pragma unroll
            for (int nt = 0; nt < 8; nt++) {
                int bb = (kw + tg) * B_SW + n0 + nt * 8;
                bf[nt][0] = Bb[bb];
                bf[nt][1] = Bb[bb + 4 * B_SW];
            }
            #pragma unroll
            for (int mt = 0; mt < 4; mt++)
                #pragma unroll
                for (int nt = 0; nt < 8; nt++)
                    mma_f16(acc[mt][nt], af[mt], bf[nt]);
        }
    };

    load_chunk(0);
    asm volatile("cp.async.commit_group;" ::: "memory");
    load_chunk(1);
    asm volatile("cp.async.commit_group;" ::: "memory");
    load_chunk(2);
    asm volatile("cp.async.commit_group;" ::: "memory");

    for (int c = 0; c < NC; c++) {
        asm volatile("cp.async.wait_group 2;" ::: "memory");
        __syncthreads();
        compute(c % 3);
        __syncthreads();
        if (c + 3 < NC) load_chunk(c + 3);
        asm volatile("cp.async.commit_group;" ::: "memory");
    }

    #pragma unroll
    for (int mt = 0; mt < 4; mt++) {
        int rbase = bm + wm * 64 + mt * 16 + g;
        #pragma unroll
        for (int half = 0; half < 2; half++) {
            int r = rbase + half * 8;
            if (r >= M) continue;
            int spos = (EPI == 2) ? (r % SEQ) : 0;
            #pragma unroll
            for (int nt = 0; nt < 8; nt++) {
                int cl = bn + wn * 64 + nt * 8 + 2 * tg;
                float2 v;
                v.x = acc[mt][nt][half * 2 + 0];
                v.y = acc[mt][nt][half * 2 + 1];
                if (EPI == 0) {
                    if (bias) { v.x += bias[cl]; v.y += bias[cl + 1]; }
                    if (res) {
                        float2 rr = *(const float2*)(res + (size_t)r * N + cl);
                        v.x += rr.x; v.y += rr.y;
                    }
                    *(float2*)(C + (size_t)r * N + cl) = v;
                } else if (EPI == 1) {
                    __half2 gh = *(const __half2*)(gateH + (size_t)r * N + cl);
                    float2 gg = __half22float2(gh);
                    float s0 = gg.x / (1.f + __expf(-gg.x)) * v.x;
                    float s1 = gg.y / (1.f + __expf(-gg.y)) * v.y;
                    *(__half2*)(outH + (size_t)r * N + cl) = __floats2half2_rn(s0, s1);
                } else if (EPI == 2) {
                    if (cl < 2048) {                  // rope on q,k pairs
                        int jj = (cl & 63) >> 1;
                        float cc = fc[(spos * 32 + jj) * 2];
                        float sn = fc[(spos * 32 + jj) * 2 + 1];
                        float x0 = v.x, x1 = v.y;
                        v.x = x0 * cc - x1 * sn;
                        v.y = x1 * cc + x0 * sn;
                    }
                    *(__half2*)(outH + (size_t)r * N + cl) = __floats2half2_rn(v.x, v.y);
                } else {                               // EPI == 3
                    *(__half2*)(outH + (size_t)r * N + cl) = __floats2half2_rn(v.x, v.y);
                }
            }
        }
    }
}

// ---------------- tensor-core flash attention (half qkv input, pre-roped) ----
// K via cp.async; V via cp.async K-major staging + vectorized smem transpose.
// Only VT is zeroed (OOB K rows land exclusively in the masked diagonal chunk,
// whose scores are overwritten; VT j>=257 must be 0.0 so p*V = 0, not 0*NaN).
#define KH_WORDS (264*36)
#define VT_WORDS (64*140)
#define VS_WORDS (264*36)
#define ATT_SMEM ((KH_WORDS+VT_WORDS+VS_WORDS)*4)

__global__ __launch_bounds__(128) void ar_fattn(const __half* __restrict__ qkv,
                                                __half* __restrict__ o)
{
    extern __shared__ uint32_t smw[];
    uint32_t* KhW = smw;
    uint32_t* VtW = smw + KH_WORDS;
    uint32_t* VsW = smw + KH_WORDS + VT_WORDS;
    int h = blockIdx.x, b = blockIdx.y;
    int tid = threadIdx.x, lane = tid & 31, warp = tid >> 5;
    int g = lane >> 2, tg = lane & 3;
    uint32_t kh_u = smem_u32(KhW);
    uint32_t vs_u = smem_u32(VsW);

    // zero VT only (overwritten for jp<129 by the transpose; tail words stay 0)
    #pragma unroll 8
    for (int i = tid; i < VT_WORDS; i += 128) VtW[i] = 0;

    const __half* kbase = qkv + (size_t)b * SEQ * 3072 + 1024 + h * 64;
    const __half* vbase = kbase + 1024;
    #pragma unroll 4
    for (int idx = tid; idx < 257 * 8; idx += 128) {      // K rows, 16B each
        int s_ = idx >> 3, cb = idx & 7;
        cp16(kh_u + (uint32_t)(s_ * 36 + 4 * cb) * 4u,
             kbase + (size_t)s_ * 3072 + cb * 8, 16);
    }
    #pragma unroll 4
    for (int idx = tid; idx < 257 * 8; idx += 128) {      // V rows -> staging
        int s_ = idx >> 3, cb = idx & 7;
        cp16(vs_u + (uint32_t)(s_ * 36 + 4 * cb) * 4u,
             vbase + (size_t)s_ * 3072 + cb * 8, 16);
    }
    asm volatile("cp.async.commit_group;" ::: "memory");
    asm volatile("cp.async.wait_group 0;" ::: "memory");
    __syncthreads();

    // transpose VS[j][d] -> VT[d][jpair] (conflict-free LDS.32 + byte_perm)
    {
        int d2 = tid >> 2, q = tid & 3;                   // d2 in [0,32): word index
        for (int jp = q; jp < 129; jp += 4) {
            int j0 = 2 * jp, j1 = j0 + 1;
            uint32_t w0 = VsW[j0 * 36 + d2];
            uint32_t w1 = (j1 < 257) ? VsW[j1 * 36 + d2] : 0u;
            VtW[(2 * d2) * 140 + jp]     = __byte_perm(w0, w1, 0x5410);
            VtW[(2 * d2 + 1) * 140 + jp] = __byte_perm(w0, w1, 0x7632);
        }
    }
    __syncthreads();

    const __half2 scale = __float2half2_rn(0.125f);

    for (int ti = 0; ti < 5; ti++) {
        int t = g_wtiles[warp * 5 + ti];
        if (t < 0) break;
        int q0 = t * 16;

        uint32_t aq[4][4];
        int r0c = min(q0 + g, 256), r1c = min(q0 + g + 8, 256);
        const __half* q0p = qkv + (size_t)(b * SEQ + r0c) * 3072 + h * 64;
        const __half* q1p = qkv + (size_t)(b * SEQ + r1c) * 3072 + h * 64;
        #pragma unroll
        for (int s = 0; s < 4; s++) {
            int dlo = s * 16 + 2 * tg, dhi = dlo + 8;
            __half2 hv;
            hv = __hmul2(*(const __half2*)(q0p + dlo), scale); aq[s][0] = *(uint32_t*)&hv;
            hv = __hmul2(*(const __half2*)(q1p + dlo), scale); aq[s][1] = *(uint32_t*)&hv;
            hv = __hmul2(*(const __half2*)(q0p + dhi), scale); aq[s][2] = *(uint32_t*)&hv;
            hv = __hmul2(*(const __half2*)(q1p + dhi), scale); aq[s][3] = *(uint32_t*)&hv;
        }

        float m0 = -1e30f, m1 = -1e30f, l0 = 0.f, l1 = 0.f;
        float acc[8][4];
        #pragma unroll
        for (int nt = 0; nt < 8; nt++)
            #pragma unroll
            for (int q = 0; q < 4; q++) acc[nt][q] = 0.f;

        int row0 = q0 + g, row1 = row0 + 8;
        int nchunks = t + 1;
        for (int ch = 0; ch < nchunks; ch++) {
            int j0c = ch * 16;
            float sc0[4] = {0.f, 0.f, 0.f, 0.f};
            float sc1[4] = {0.f, 0.f, 0.f, 0.f};
            #pragma unroll
            for (int s = 0; s < 4; s++) {
                uint32_t b0[2], b1[2];
                int base0 = (j0c + g) * 36 + 8 * s + tg;
                b0[0] = KhW[base0];
                b0[1] = KhW[base0 + 4];
                b1[0] = KhW[base0 + 8 * 36];
                b1[1] = KhW[base0 + 8 * 36 + 4];
                mma_f16(sc0, aq[s], b0);
                mma_f16(sc1, aq[s], b1);
            }
            if (ch == t) {
                int cb = j0c + 2 * tg;
                if (cb     > row0) sc0[0] = -1e30f;
                if (cb + 1 > row0) sc0[1] = -1e30f;
                if (cb     > row1) sc0[2] = -1e30f;
                if (cb + 1 > row1) sc0[3] = -1e30f;
                if (cb + 8 > row0) sc1[0] = -1e30f;
                if (cb + 9 > row0) sc1[1] = -1e30f;
                if (cb + 8 > row1) sc1[2] = -1e30f;
                if (cb + 9 > row1) sc1[3] = -1e30f;
            }
            float cm0 = fmaxf(fmaxf(sc0[0], sc0[1]), fmaxf(sc1[0], sc1[1]));
            float cm1 = fmaxf(fmaxf(sc0[2], sc0[3]), fmaxf(sc1[2], sc1[3]));
            cm0 = fmaxf(cm0, __shfl_xor_sync(0xffffffffu, cm0, 1));
            cm0 = fmaxf(cm0, __shfl_xor_sync(0xffffffffu, cm0, 2));
            cm1 = fmaxf(cm1, __shfl_xor_sync(0xffffffffu, cm1, 1));
            cm1 = fmaxf(cm1, __shfl_xor_sync(0xffffffffu, cm1, 2));
            float nm0 = fmaxf(m0, cm0), nm1 = fmaxf(m1, cm1);
            float corr0 = __expf(m0 - nm0), corr1 = __expf(m1 - nm1);
            float p00 = __expf(sc0[0] - nm0), p01 = __expf(sc0[1] - nm0);
            float p02 = __expf(sc0[2] - nm1), p03 = __expf(sc0[3] - nm1);
            float p10 = __expf(sc1[0] - nm0), p11 = __expf(sc1[1] - nm0);
            float p12 = __expf(sc1[2] - nm1), p13 = __expf(sc1[3] - nm1);
            float ps0 = (p00 + p01) + (p10 + p11);
            float ps1 = (p02 + p03) + (p12 + p13);
            ps0 += __shfl_xor_sync(0xffffffffu, ps0, 1);
            ps0 += __shfl_xor_sync(0xffffffffu, ps0, 2);
            ps1 += __shfl_xor_sync(0xffffffffu, ps1, 1);
            ps1 += __shfl_xor_sync(0xffffffffu, ps1, 2);
            l0 = l0 * corr0 + ps0;
            l1 = l1 * corr1 + ps1;
            m0 = nm0; m1 = nm1;

            uint32_t ap[4];
            ap[0] = pack_h2(p00, p01);
            ap[1] = pack_h2(p02, p03);
            ap[2] = pack_h2(p10, p11);
            ap[3] = pack_h2(p12, p13);

            int jh = (j0c >> 1) + tg;
            #pragma unroll
            for (int nt = 0; nt < 8; nt++) {
                acc[nt][0] *= corr0; acc[nt][1] *= corr0;
                acc[nt][2] *= corr1; acc[nt][3] *= corr1;
                uint32_t bv[2];
                int vb = (nt * 8 + g) * 140 + jh;
                bv[0] = VtW[vb];
                bv[1] = VtW[vb + 4];
                mma_f16(acc[nt], ap, bv);
            }
        }

        float inv0 = 1.f / l0, inv1 = 1.f / l1;
        __half* ob = o + (size_t)b * SEQ * EMBED + h * 64 + 2 * tg;
        if (row0 < SEQ) {
            __half* orow = ob + (size_t)row0 * EMBED;
            #pragma unroll
            for (int nt = 0; nt < 8; nt++)
                *(__half2*)(orow + nt * 8) =
                    __floats2half2_rn(acc[nt][0] * inv0, acc[nt][1] * inv0);
        }
        if (row1 < SEQ) {
            __half* orow = ob + (size_t)row1 * EMBED;
            #pragma unroll
            for (int nt = 0; nt < 8; nt++)
                *(__half2*)(orow + nt * 8) =
                    __floats2half2_rn(acc[nt][2] * inv1, acc[nt][3] * inv1);
        }
    }
}

// ---------------- weight convert: [K][N] f32 -> [K/2][N] half2 (wide) --------
__global__ __launch_bounds__(256) void ar_b2h(const float* __restrict__ in,
                                              __half2* __restrict__ out,
                                              int K, int N) {
    size_t z = blockIdx.z;
    in  += z * (size_t)K * N;
    out += z * (size_t)(K / 2) * N;
    int total = (K / 2) * (N / 4);
    int idx = blockIdx.x * blockDim.x + threadIdx.x;
    if (idx >= total) return;
    int nq = N / 4;
    int k2 = idx / nq, n4 = (idx - k2 * nq) * 4;
    float4 lo = *(const float4*)(in + (size_t)(2 * k2) * N + n4);
    float4 hi = *(const float4*)(in + (size_t)(2 * k2 + 1) * N + n4);
    __half2* op = out + (size_t)k2 * N + n4;
    op[0] = __floats2half2_rn(lo.x, hi.x);
    op[1] = __floats2half2_rn(lo.y, hi.y);
    op[2] = __floats2half2_rn(lo.z, hi.z);
    op[3] = __floats2half2_rn(lo.w, hi.w);
}

// ---------------- activation convert: f32 -> f16 flat ------------------------
__global__ void ar_f2h(const float* __restrict__ in, __half2* __restrict__ out,
                       size_t n4) {
    size_t i = (size_t)blockIdx.x * blockDim.x + threadIdx.x;
    if (i < n4) {
        float4 v = ((const float4*)in)[i];
        out[2 * i]     = __floats2half2_rn(v.x, v.y);
        out[2 * i + 1] = __floats2half2_rn(v.z, v.w);
    }
}

// ---------------- reductions ------------------------------------------------
__device__ __forceinline__ float block_sum(float v, float* red) {
    int tid = threadIdx.x;
    #pragma unroll
    for (int o = 16; o > 0; o >>= 1) v += __shfl_xor_sync(0xffffffffu, v, o);
    if ((tid & 31) == 0) red[tid >> 5] = v;
    __syncthreads();
    if (tid == 0) {
        float s = red[0];
        int nw = blockDim.x >> 5;
        for (int i = 1; i < nw; i++) s += red[i];
        red[0] = s;
    }
    __syncthreads();
    float r = red[0];
    __syncthreads();
    return r;
}

// ---------------- rope frequency table --------------------------------------
__global__ void ar_freqs(float* __restrict__ fc) {
    int t = blockIdx.x * blockDim.x + threadIdx.x;
    if (t >= SEQ * 32) return;
    int p = t >> 5, j = t & 31;
    float c = 0.f, s = 0.f;
    if (p > 0) {                       // cls token keeps cos=sin=0 (ref!)
        int pp = p - 1, yy = pp >> 4, xx = pp & 15;
        int i = j & 15;
        float fr = powf(10000.0f, -(float)i * (1.0f / 16.0f));
        float tt = (j < 16) ? (float)yy : (float)xx;
        float ang = tt * fr;
        c = cosf(ang); s = sinf(ang);
    }
    fc[2 * t] = c;
    fc[2 * t + 1] = s;
}

// ---------------- assemble (cond | patch) + pos + LayerNorm ------------------
__global__ __launch_bounds__(256) void ar_assemble_ln(
    const float* __restrict__ patch, const float* __restrict__ condr,
    const float* __restrict__ pos, const float* __restrict__ g,
    const float* __restrict__ bta, float* __restrict__ h)
{
    __shared__ float buf[EMBED];
    __shared__ float red[8];
    int m = blockIdx.x, tid = threadIdx.x;
    int b = m / SEQ, s = m % SEQ;
    const float* src = (s == 0) ? (condr + (size_t)b * EMBED)
                                : (patch + ((size_t)(b * 256 + s - 1)) * EMBED);
    float lsum = 0.f;
    for (int d = tid; d < EMBED; d += 256) {
        float v = src[d] + pos[(size_t)s * EMBED + d];
        buf[d] = v; lsum += v;
    }
    float mean = block_sum(lsum, red) * (1.f / EMBED);
    float ls2 = 0.f;
    for (int d = tid; d < EMBED; d += 256) {
        float dv = buf[d] - mean; ls2 += dv * dv;
    }
    float var = block_sum(ls2, red) * (1.f / EMBED);
    float rinv = rsqrtf(var + 1e-6f);
    for (int d = tid; d < EMBED; d += 256)
        h[(size_t)m * EMBED + d] = (buf[d] - mean) * rinv * g[d] + bta[d];
}

// ---------------- RMSNorm (float4 loads, half output) ------------------------
__global__ __launch_bounds__(256) void ar_rmsnorm(
    const float* __restrict__ x, const float* __restrict__ w, __half* __restrict__ out)
{
    __shared__ float red[8];
    int m = blockIdx.x, tid = threadIdx.x;
    float4 v = ((const float4*)(x + (size_t)m * EMBED))[tid];
    float ss = v.x * v.x + v.y * v.y + v.z * v.z + v.w * v.w;
    ss = block_sum(ss, red);
    float r = rsqrtf(ss * (1.f / EMBED) + 1e-5f);
    float4 wv = ((const float4*)w)[tid];
    __half2* o2 = (__half2*)(out + (size_t)m * EMBED);
    o2[2 * tid]     = __floats2half2_rn(v.x * r * wv.x, v.y * r * wv.y);
    o2[2 * tid + 1] = __floats2half2_rn(v.z * r * wv.z, v.w * r * wv.w);
}

// ---------------- host orchestration ----------------------------------------
static inline void launch_gemm(const __half* A, const __half* B, const float* bias,
                               const float* res, float* C, int M, int N, int K) {
    dim3 grid(N / BN, (M + BM - 1) / BM);
    ar_gemm_f16<0><<<grid, 128, G_SMEM>>>(A, (const __half2*)B, bias, res, C,
                                          nullptr, nullptr, nullptr, M, N, K);
}

static inline void launch_gemm_silu(const __half* A, const __half* B,
                                    const __half* gateH, __half* outH,
                                    int M, int N, int K) {
    dim3 grid(N / BN, (M + BM - 1) / BM);
    ar_gemm_f16<1><<<grid, 128, G_SMEM>>>(A, (const __half2*)B, nullptr, nullptr,
                                          nullptr, gateH, outH, nullptr, M, N, K);
}

static inline void launch_gemm_rope(const __half* A, const __half* B,
                                    __half* outH, const float* fc,
                                    int M, int N, int K) {
    dim3 grid(N / BN, (M + BM - 1) / BM);
    ar_gemm_f16<2><<<grid, 128, G_SMEM>>>(A, (const __half2*)B, nullptr, nullptr,
                                          nullptr, nullptr, outH, fc, M, N, K);
}

static inline void launch_gemm_h(const __half* A, const __half* B,
                                 __half* outH, int M, int N, int K) {
    dim3 grid(N / BN, (M + BM - 1) / BM);
    ar_gemm_f16<3><<<grid, 128, G_SMEM>>>(A, (const __half2*)B, nullptr, nullptr,
                                          nullptr, nullptr, outH, nullptr, M, N, K);
}

static inline void launch_b2h(const float* in, __half* out, int K, int N, int L) {
    int total = (K / 2) * (N / 4);
    ar_b2h<<<dim3((total + 255) / 256, 1, L), 256>>>(in, (__half2*)out, K, N);
}

static inline void launch_f2h(const float* in, __half* out, size_t n) {
    size_t n4 = n / 4;
    ar_f2h<<<(unsigned)((n4 + 255) / 256), 256>>>(in, (__half2*)out, n4);
}

extern "C" void kernel_launch(void* const* d_in, const int* in_sizes, int n_in,
                              void* d_out, int out_size)
{
    const float* x       = (const float*)d_in[0];
    const float* cond    = (const float*)d_in[1];
    const float* patch_w = (const float*)d_in[2];
    const float* patch_b = (const float*)d_in[3];
    const float* ln_g    = (const float*)d_in[4];
    const float* ln_b    = (const float*)d_in[5];
    const float* pos     = (const float*)d_in[6];
    const float* cond_w  = (const float*)d_in[7];
    const float* cond_b  = (const float*)d_in[8];
    const float* wqkv    = (const float*)d_in[9];
    const float* wo      = (const float*)d_in[10];
    const float* w1      = (const float*)d_in[11];
    const float* w2      = (const float*)d_in[12];
    const float* w3      = (const float*)d_in[13];
    const float* anw     = (const float*)d_in[14];
    const float* fnw     = (const float*)d_in[15];
    float* h = (float*)d_out;

    __half *pa, *po, *pu, *pxh, *pch, *pwt;
    float *pqkv, *pf1, *pfc;
    cudaGetSymbolAddress((void**)&pa,   g_a);
    cudaGetSymbolAddress((void**)&po,   g_o);
    cudaGetSymbolAddress((void**)&pu,   g_u);
    cudaGetSymbolAddress((void**)&pxh,  g_xh);
    cudaGetSymbolAddress((void**)&pch,  g_ch);
    cudaGetSymbolAddress((void**)&pwt,  g_wt);
    cudaGetSymbolAddress((void**)&pqkv, g_qkv);
    cudaGetSymbolAddress((void**)&pf1,  g_f1);
    cudaGetSymbolAddress((void**)&pfc,  g_fc);

    __half* pqh = (__half*)pqkv;    // half view: roped qkv
    __half* pgh = (__half*)pf1;     // half view: w1 gate

    cudaFuncSetAttribute(ar_gemm_f16<0>, cudaFuncAttributeMaxDynamicSharedMemorySize,
                         G_SMEM);
    cudaFuncSetAttribute(ar_gemm_f16<1>, cudaFuncAttributeMaxDynamicSharedMemorySize,
                         G_SMEM);
    cudaFuncSetAttribute(ar_gemm_f16<2>, cudaFuncAttributeMaxDynamicSharedMemorySize,
                         G_SMEM);
    cudaFuncSetAttribute(ar_gemm_f16<3>, cudaFuncAttributeMaxDynamicSharedMemorySize,
                         G_SMEM);
    cudaFuncSetAttribute(ar_fattn, cudaFuncAttributeMaxDynamicSharedMemorySize,
                         ATT_SMEM);

    __half* qkvH   = pwt + OFF_QKV;
    __half* woH    = pwt + OFF_WO;
    __half* w1H    = pwt + OFF_W1;
    __half* w3H    = pwt + OFF_W3;
    __half* w2H    = pwt + OFF_W2;
    __half* patchH = pwt + OFF_PATCH;
    __half* condH  = pwt + OFF_COND;

    // convert weights (k-pair interleaved) + A-side raw inputs to half
    launch_b2h(wqkv,    qkvH,   1024, 3072, NB);
    launch_b2h(wo,      woH,    1024, 1024, NB);
    launch_b2h(w1,      w1H,    1024, HIDDEN, NB);
    launch_b2h(w3,      w3H,    1024, HIDDEN, NB);
    launch_b2h(w2,      w2H,    HIDDEN, 1024, NB);
    launch_b2h(patch_w, patchH, 768, 1024, 1);
    launch_b2h(cond_w,  condH,  1024, 1024, 1);
    launch_f2h(x,    pxh, (size_t)8192 * 768);
    launch_f2h(cond, pch, (size_t)32 * 1024);

    // rope table
    ar_freqs<<<(SEQ * 32 + 255) / 256, 256>>>(pfc);
    // patch embed -> g_f1 (f32) ; cond embed -> g_qkv (f32, temp)
    launch_gemm(pxh, patchH, patch_b, nullptr, pf1, BATCH * 256, EMBED, 768);
    launch_gemm(pch, condH, cond_b, nullptr, pqkv, BATCH, EMBED, EMBED);
    // assemble + pos + layernorm -> h (d_out)
    ar_assemble_ln<<<MROWS, 256>>>(pf1, pqkv, pos, ln_g, ln_b, h);

    for (int l = 0; l < NB; l++) {
        __half* qkv_l = qkvH + (size_t)l * 1024 * 3072;
        __half* wo_l  = woH  + (size_t)l * 1024 * 1024;
        __half* w1_l  = w1H  + (size_t)l * 1024 * HIDDEN;
        __half* w3_l  = w3H  + (size_t)l * 1024 * HIDDEN;
        __half* w2_l  = w2H  + (size_t)l * HIDDEN * 1024;

        ar_rmsnorm<<<MROWS, 256>>>(h, anw + (size_t)l * EMBED, pa);
        // qkv GEMM with fused rope, half output
        launch_gemm_rope(pa, qkv_l, pqh, pfc, MROWS, 3 * EMBED, EMBED);
        ar_fattn<<<dim3(HEADS, BATCH), 128, ATT_SMEM>>>(pqh, po);
        launch_gemm(po, wo_l, nullptr, h, h, MROWS, EMBED, EMBED);

        ar_rmsnorm<<<MROWS, 256>>>(h, fnw + (size_t)l * EMBED, pa);
        // w1 GEMM -> half gate
        launch_gemm_h(pa, w1_l, pgh, MROWS, HIDDEN, EMBED);
        // w3 GEMM with fused silu(gate)*acc -> half u
        launch_gemm_silu(pa, w3_l, pgh, pu, MROWS, HIDDEN, EMBED);
        launch_gemm(pu, w2_l, nullptr, h, h, MROWS, EMBED, HIDDEN);
    }
}

// round 16
// speedup vs baseline: 1.1997x; 1.0814x over previous
#include <cuda_runtime.h>
#include <cuda_fp16.h>
#include <math.h>
#include <stdint.h>

#define EMBED   1024
#define HEADS   16
#define HD      64
#define NB      12
#define SEQ     257
#define BATCH   32
#define MROWS   (BATCH*SEQ)      // 8224
#define HIDDEN  2816

// ---------------- scratch (device globals; no allocations allowed) ----------
__device__ __align__(256) __half g_a[MROWS*EMBED];      // rmsnorm out (half, GEMM A)
__device__ __align__(256) __half g_o[MROWS*EMBED];      // attn out (half, GEMM A)
__device__ __align__(256) __half g_u[MROWS*HIDDEN];     // silu(gate)*up (half, GEMM A)
__device__ __align__(256) __half g_xh[8192*768];        // x (half)
__device__ __align__(256) __half g_ch[32*1024];         // cond (half)
__device__ __align__(256) float  g_qkv[MROWS*3*EMBED];  // cond-out f32 / half qkv (roped)
__device__ __align__(256) float  g_f1[MROWS*HIDDEN];    // patch-out f32
__device__ __align__(256) float  g_fc[SEQ*32*2];        // rope cos/sin table

// half weights, k-pair interleaved: [K/2][N] half2.
// GU = merged w1/w3: [K/2][2*HIDDEN], col 2j = w1 col j, col 2j+1 = w3 col j.
#define OFF_QKV   ((size_t)0)
#define OFF_WO    (OFF_QKV + (size_t)NB*1024*3072)
#define OFF_GU    (OFF_WO  + (size_t)NB*1024*1024)
#define OFF_W2    (OFF_GU  + (size_t)NB*1024*(2*HIDDEN))
#define OFF_PATCH (OFF_W2  + (size_t)NB*HIDDEN*1024)
#define OFF_COND  (OFF_PATCH + (size_t)768*1024)
#define WT_TOTAL  (OFF_COND + (size_t)1024*1024)
__device__ __align__(256) __half g_wt[WT_TOTAL];

// attention warp->q-tile schedule (chunk-balanced 38/38/39/38)
__constant__ int g_wtiles[20] = {16,12,5,1,-1, 15,13,4,2,-1, 14,11,6,3,0, 10,9,8,7,-1};

// ---------------- helpers ----------------------------------------------------
__device__ __forceinline__ uint32_t smem_u32(const void* p) {
    uint32_t a;
    asm("{ .reg .u64 t; cvta.to.shared.u64 t, %1; cvt.u32.u64 %0, t; }" : "=r"(a) : "l"(p));
    return a;
}

__device__ __forceinline__ uint32_t pack_h2(float a, float b) {
    __half2 h = __floats2half2_rn(a, b);
    return *(uint32_t*)&h;
}

__device__ __forceinline__ void mma_f16(float c[4], const uint32_t a[4],
                                        const uint32_t b[2]) {
    asm volatile(
        "mma.sync.aligned.m16n8k16.row.col.f32.f16.f16.f32 "
        "{%0,%1,%2,%3}, {%4,%5,%6,%7}, {%8,%9}, {%0,%1,%2,%3};"
        : "+f"(c[0]), "+f"(c[1]), "+f"(c[2]), "+f"(c[3])
        : "r"(a[0]), "r"(a[1]), "r"(a[2]), "r"(a[3]), "r"(b[0]), "r"(b[1]));
}

__device__ __forceinline__ void cp16(uint32_t dst, const void* src, int sz) {
    asm volatile("cp.async.cg.shared.global [%0], [%1], 16, %2;"
        :: "r"(dst), "l"(src), "r"(sz) : "memory");
}

// ---------------- pipelined FP16 tensor-core GEMM ----------------------------
// Template-specialized epilogues (compile-time, separate instantiations):
//   EPI=0: C(f32) = acc (+bias) (+res)                         [proven hot path]
//   EPI=1: merged gate-up: acc cols (2j,2j+1)=(gate_j,up_j);
//          outH[r][j] = silu(gate)*up, half                     [GU GEMM]
//   EPI=2: outH(half) = rope(acc) for cols<2048, else acc       [qkv GEMM]
#define BM     128
#define BN     128
#define BK     64
#define A_SW   36
#define B_SW   136
#define A_WORDS (BM*A_SW)
#define B_WORDS ((BK/2)*B_SW)
#define ST_WORDS (A_WORDS+B_WORDS)
#define G_SMEM (3*ST_WORDS*4)

template<int EPI>
__global__ __launch_bounds__(128) void ar_gemm_f16(
    const __half* __restrict__ A, const __half2* __restrict__ B2,
    const float* __restrict__ bias, const float* __restrict__ res,
    float* __restrict__ C, __half* __restrict__ outH,
    const float* __restrict__ fc, int M, int N, int K)
{
    extern __shared__ uint32_t sm[];
    uint32_t sm_u = smem_u32(sm);

    int tid = threadIdx.x, lane = tid & 31, warp = tid >> 5;
    int wm = warp & 1, wn = warp >> 1;
    int bm = blockIdx.y * BM, bn = blockIdx.x * BN;
    int g = lane >> 2, tg = lane & 3;

    float acc[4][8][4];
    #pragma unroll
    for (int i = 0; i < 4; i++)
        #pragma unroll
        for (int j = 0; j < 8; j++)
            #pragma unroll
            for (int t = 0; t < 4; t++) acc[i][j][t] = 0.f;

    const int NC = K / BK;

    auto load_chunk = [&](int cidx) {
        int s = cidx % 3;
        int k0 = cidx * BK;
        uint32_t st = sm_u + (uint32_t)(s * ST_WORDS) * 4u;
        #pragma unroll
        for (int i = 0; i < 8; i++) {
            int idx = tid + (i << 7);
            int r = idx >> 3, cc = idx & 7;
            uint32_t dst = st + (uint32_t)(r * A_SW + cc * 4) * 4u;
            int gm = bm + r;
            bool v = (gm < M);
            const __half* src = A + (size_t)(v ? gm : 0) * K + k0 + cc * 8;
            cp16(dst, src, v ? 16 : 0);
        }
        #pragma unroll
        for (int i = 0; i < 8; i++) {
            int idx = tid + (i << 7);
            int r = idx >> 5, cc = idx & 31;
            uint32_t dst = st + (uint32_t)(A_WORDS + r * B_SW + cc * 4) * 4u;
            const __half2* src = B2 + (size_t)(k0 / 2 + r) * N + bn + cc * 4;
            cp16(dst, src, 16);
        }
    };

    auto compute = [&](int s) {
        const uint32_t* St = sm + s * ST_WORDS;
        const uint32_t* Ab = St;
        const uint32_t* Bb = St + A_WORDS;
        int m0 = wm * 64 + g;
        int n0 = wn * 64 + g;
        #pragma unroll
        for (int ks = 0; ks < 4; ks++) {
            int kw = ks * 8;
            uint32_t af[4][4];
            #pragma unroll
            for (int mt = 0; mt < 4; mt++) {
                int base = (m0 + mt * 16) * A_SW + kw + tg;
                af[mt][0] = Ab[base];
                af[mt][1] = Ab[base + 8 * A_SW];
                af[mt][2] = Ab[base + 4];
                af[mt][3] = Ab[base + 8 * A_SW + 4];
            }
            uint32_t bf[8][2];
            #pragma unroll
            for (int nt = 0; nt < 8; nt++) {
                int bb = (kw + tg) * B_SW + n0 + nt * 8;
                bf[nt][0] = Bb[bb];
                bf[nt][1] = Bb[bb + 4 * B_SW];
            }
            #pragma unroll
            for (int mt = 0; mt < 4; mt++)
                #pragma unroll
                for (int nt = 0; nt < 8; nt++)
                    mma_f16(acc[mt][nt], af[mt], bf[nt]);
        }
    };

    load_chunk(0);
    asm volatile("cp.async.commit_group;" ::: "memory");
    load_chunk(1);
    asm volatile("cp.async.commit_group;" ::: "memory");
    load_chunk(2);
    asm volatile("cp.async.commit_group;" ::: "memory");

    for (int c = 0; c < NC; c++) {
        asm volatile("cp.async.wait_group 2;" ::: "memory");
        __syncthreads();
        compute(c % 3);
        __syncthreads();
        if (c + 3 < NC) load_chunk(c + 3);
        asm volatile("cp.async.commit_group;" ::: "memory");
    }

    #pragma unroll
    for (int mt = 0; mt < 4; mt++) {
        int rbase = bm + wm * 64 + mt * 16 + g;
        #pragma unroll
        for (int half = 0; half < 2; half++) {
            int r = rbase + half * 8;
            if (r >= M) continue;
            int spos = (EPI == 2) ? (r % SEQ) : 0;
            #pragma unroll
            for (int nt = 0; nt < 8; nt++) {
                int cl = bn + wn * 64 + nt * 8 + 2 * tg;
                float2 v;
                v.x = acc[mt][nt][half * 2 + 0];
                v.y = acc[mt][nt][half * 2 + 1];
                if (EPI == 0) {
                    if (bias) { v.x += bias[cl]; v.y += bias[cl + 1]; }
                    if (res) {
                        float2 rr = *(const float2*)(res + (size_t)r * N + cl);
                        v.x += rr.x; v.y += rr.y;
                    }
                    *(float2*)(C + (size_t)r * N + cl) = v;
                } else if (EPI == 1) {
                    // v.x = gate (w1 col j), v.y = up (w3 col j), j = cl/2
                    float s0 = v.x / (1.f + __expf(-v.x)) * v.y;
                    outH[(size_t)r * (N >> 1) + (cl >> 1)] = __float2half(s0);
                } else {                               // EPI == 2
                    if (cl < 2048) {                  // rope on q,k pairs
                        int jj = (cl & 63) >> 1;
                        float cc = fc[(spos * 32 + jj) * 2];
                        float sn = fc[(spos * 32 + jj) * 2 + 1];
                        float x0 = v.x, x1 = v.y;
                        v.x = x0 * cc - x1 * sn;
                        v.y = x1 * cc + x0 * sn;
                    }
                    *(__half2*)(outH + (size_t)r * N + cl) = __floats2half2_rn(v.x, v.y);
                }
            }
        }
    }
}

// ---------------- tensor-core flash attention (half qkv input, pre-roped) ----
#define KH_WORDS (264*36)
#define VT_WORDS (64*140)
#define VS_WORDS (264*36)
#define ATT_SMEM ((KH_WORDS+VT_WORDS+VS_WORDS)*4)

__global__ __launch_bounds__(128) void ar_fattn(const __half* __restrict__ qkv,
                                                __half* __restrict__ o)
{
    extern __shared__ uint32_t smw[];
    uint32_t* KhW = smw;
    uint32_t* VtW = smw + KH_WORDS;
    uint32_t* VsW = smw + KH_WORDS + VT_WORDS;
    int h = blockIdx.x, b = blockIdx.y;
    int tid = threadIdx.x, lane = tid & 31, warp = tid >> 5;
    int g = lane >> 2, tg = lane & 3;
    uint32_t kh_u = smem_u32(KhW);
    uint32_t vs_u = smem_u32(VsW);

    #pragma unroll 8
    for (int i = tid; i < VT_WORDS; i += 128) VtW[i] = 0;

    const __half* kbase = qkv + (size_t)b * SEQ * 3072 + 1024 + h * 64;
    const __half* vbase = kbase + 1024;
    #pragma unroll 4
    for (int idx = tid; idx < 257 * 8; idx += 128) {
        int s_ = idx >> 3, cb = idx & 7;
        cp16(kh_u + (uint32_t)(s_ * 36 + 4 * cb) * 4u,
             kbase + (size_t)s_ * 3072 + cb * 8, 16);
    }
    #pragma unroll 4
    for (int idx = tid; idx < 257 * 8; idx += 128) {
        int s_ = idx >> 3, cb = idx & 7;
        cp16(vs_u + (uint32_t)(s_ * 36 + 4 * cb) * 4u,
             vbase + (size_t)s_ * 3072 + cb * 8, 16);
    }
    asm volatile("cp.async.commit_group;" ::: "memory");
    asm volatile("cp.async.wait_group 0;" ::: "memory");
    __syncthreads();

    {
        int d2 = tid >> 2, q = tid & 3;
        for (int jp = q; jp < 129; jp += 4) {
            int j0 = 2 * jp, j1 = j0 + 1;
            uint32_t w0 = VsW[j0 * 36 + d2];
            uint32_t w1 = (j1 < 257) ? VsW[j1 * 36 + d2] : 0u;
            VtW[(2 * d2) * 140 + jp]     = __byte_perm(w0, w1, 0x5410);
            VtW[(2 * d2 + 1) * 140 + jp] = __byte_perm(w0, w1, 0x7632);
        }
    }
    __syncthreads();

    const __half2 scale = __float2half2_rn(0.125f);

    for (int ti = 0; ti < 5; ti++) {
        int t = g_wtiles[warp * 5 + ti];
        if (t < 0) break;
        int q0 = t * 16;

        uint32_t aq[4][4];
        int r0c = min(q0 + g, 256), r1c = min(q0 + g + 8, 256);
        const __half* q0p = qkv + (size_t)(b * SEQ + r0c) * 3072 + h * 64;
        const __half* q1p = qkv + (size_t)(b * SEQ + r1c) * 3072 + h * 64;
        #pragma unroll
        for (int s = 0; s < 4; s++) {
            int dlo = s * 16 + 2 * tg, dhi = dlo + 8;
            __half2 hv;
            hv = __hmul2(*(const __half2*)(q0p + dlo), scale); aq[s][0] = *(uint32_t*)&hv;
            hv = __hmul2(*(const __half2*)(q1p + dlo), scale); aq[s][1] = *(uint32_t*)&hv;
            hv = __hmul2(*(const __half2*)(q0p + dhi), scale); aq[s][2] = *(uint32_t*)&hv;
            hv = __hmul2(*(const __half2*)(q1p + dhi), scale); aq[s][3] = *(uint32_t*)&hv;
        }

        float m0 = -1e30f, m1 = -1e30f, l0 = 0.f, l1 = 0.f;
        float acc[8][4];
        #pragma unroll
        for (int nt = 0; nt < 8; nt++)
            #pragma unroll
            for (int q = 0; q < 4; q++) acc[nt][q] = 0.f;

        int row0 = q0 + g, row1 = row0 + 8;
        int nchunks = t + 1;
        for (int ch = 0; ch < nchunks; ch++) {
            int j0c = ch * 16;
            float sc0[4] = {0.f, 0.f, 0.f, 0.f};
            float sc1[4] = {0.f, 0.f, 0.f, 0.f};
            #pragma unroll
            for (int s = 0; s < 4; s++) {
                uint32_t b0[2], b1[2];
                int base0 = (j0c + g) * 36 + 8 * s + tg;
                b0[0] = KhW[base0];
                b0[1] = KhW[base0 + 4];
                b1[0] = KhW[base0 + 8 * 36];
                b1[1] = KhW[base0 + 8 * 36 + 4];
                mma_f16(sc0, aq[s], b0);
                mma_f16(sc1, aq[s], b1);
            }
            if (ch == t) {
                int cb = j0c + 2 * tg;
                if (cb     > row0) sc0[0] = -1e30f;
                if (cb + 1 > row0) sc0[1] = -1e30f;
                if (cb     > row1) sc0[2] = -1e30f;
                if (cb + 1 > row1) sc0[3] = -1e30f;
                if (cb + 8 > row0) sc1[0] = -1e30f;
                if (cb + 9 > row0) sc1[1] = -1e30f;
                if (cb + 8 > row1) sc1[2] = -1e30f;
                if (cb + 9 > row1) sc1[3] = -1e30f;
            }
            float cm0 = fmaxf(fmaxf(sc0[0], sc0[1]), fmaxf(sc1[0], sc1[1]));
            float cm1 = fmaxf(fmaxf(sc0[2], sc0[3]), fmaxf(sc1[2], sc1[3]));
            cm0 = fmaxf(cm0, __shfl_xor_sync(0xffffffffu, cm0, 1));
            cm0 = fmaxf(cm0, __shfl_xor_sync(0xffffffffu, cm0, 2));
            cm1 = fmaxf(cm1, __shfl_xor_sync(0xffffffffu, cm1, 1));
            cm1 = fmaxf(cm1, __shfl_xor_sync(0xffffffffu, cm1, 2));
            float nm0 = fmaxf(m0, cm0), nm1 = fmaxf(m1, cm1);
            float corr0 = __expf(m0 - nm0), corr1 = __expf(m1 - nm1);
            float p00 = __expf(sc0[0] - nm0), p01 = __expf(sc0[1] - nm0);
            float p02 = __expf(sc0[2] - nm1), p03 = __expf(sc0[3] - nm1);
            float p10 = __expf(sc1[0] - nm0), p11 = __expf(sc1[1] - nm0);
            float p12 = __expf(sc1[2] - nm1), p13 = __expf(sc1[3] - nm1);
            float ps0 = (p00 + p01) + (p10 + p11);
            float ps1 = (p02 + p03) + (p12 + p13);
            ps0 += __shfl_xor_sync(0xffffffffu, ps0, 1);
            ps0 += __shfl_xor_sync(0xffffffffu, ps0, 2);
            ps1 += __shfl_xor_sync(0xffffffffu, ps1, 1);
            ps1 += __shfl_xor_sync(0xffffffffu, ps1, 2);
            l0 = l0 * corr0 + ps0;
            l1 = l1 * corr1 + ps1;
            m0 = nm0; m1 = nm1;

            uint32_t ap[4];
            ap[0] = pack_h2(p00, p01);
            ap[1] = pack_h2(p02, p03);
            ap[2] = pack_h2(p10, p11);
            ap[3] = pack_h2(p12, p13);

            int jh = (j0c >> 1) + tg;
            #pragma unroll
            for (int nt = 0; nt < 8; nt++) {
                acc[nt][0] *= corr0; acc[nt][1] *= corr0;
                acc[nt][2] *= corr1; acc[nt][3] *= corr1;
                uint32_t bv[2];
                int vb = (nt * 8 + g) * 140 + jh;
                bv[0] = VtW[vb];
                bv[1] = VtW[vb + 4];
                mma_f16(acc[nt], ap, bv);
            }
        }

        float inv0 = 1.f / l0, inv1 = 1.f / l1;
        __half* ob = o + (size_t)b * SEQ * EMBED + h * 64 + 2 * tg;
        if (row0 < SEQ) {
            __half* orow = ob + (size_t)row0 * EMBED;
            #pragma unroll
            for (int nt = 0; nt < 8; nt++)
                *(__half2*)(orow + nt * 8) =
                    __floats2half2_rn(acc[nt][0] * inv0, acc[nt][1] * inv0);
        }
        if (row1 < SEQ) {
            __half* orow = ob + (size_t)row1 * EMBED;
            #pragma unroll
            for (int nt = 0; nt < 8; nt++)
                *(__half2*)(orow + nt * 8) =
                    __floats2half2_rn(acc[nt][2] * inv1, acc[nt][3] * inv1);
        }
    }
}

// ---------------- weight convert: [K][N] f32 -> [K/2][N] half2 (wide) --------
__global__ __launch_bounds__(256) void ar_b2h(const float* __restrict__ in,
                                              __half2* __restrict__ out,
                                              int K, int N) {
    size_t z = blockIdx.z;
    in  += z * (size_t)K * N;
    out += z * (size_t)(K / 2) * N;
    int total = (K / 2) * (N / 4);
    int idx = blockIdx.x * blockDim.x + threadIdx.x;
    if (idx >= total) return;
    int nq = N / 4;
    int k2 = idx / nq, n4 = (idx - k2 * nq) * 4;
    float4 lo = *(const float4*)(in + (size_t)(2 * k2) * N + n4);
    float4 hi = *(const float4*)(in + (size_t)(2 * k2 + 1) * N + n4);
    __half2* op = out + (size_t)k2 * N + n4;
    op[0] = __floats2half2_rn(lo.x, hi.x);
    op[1] = __floats2half2_rn(lo.y, hi.y);
    op[2] = __floats2half2_rn(lo.z, hi.z);
    op[3] = __floats2half2_rn(lo.w, hi.w);
}

// ---------------- merged gate-up convert -------------------------------------
// w1,w3: [NB][K][HIDDEN] f32 -> gu: [NB][K/2][2*HIDDEN] half2,
// out col 2j = w1 col j, col 2j+1 = w3 col j (k-pair packed in the half2).
__global__ __launch_bounds__(256) void ar_gu2h(const float* __restrict__ w1,
                                               const float* __restrict__ w3,
                                               __half2* __restrict__ out,
                                               int K, int N) {
    size_t z = blockIdx.z;
    w1  += z * (size_t)K * N;
    w3  += z * (size_t)K * N;
    out += z * (size_t)(K / 2) * (2 * N);
    int total = (K / 2) * (N / 4);
    int idx = blockIdx.x * blockDim.x + threadIdx.x;
    if (idx >= total) return;
    int nq = N / 4;
    int k2 = idx / nq, n4 = (idx - k2 * nq) * 4;
    float4 a_lo = *(const float4*)(w1 + (size_t)(2 * k2) * N + n4);
    float4 a_hi = *(const float4*)(w1 + (size_t)(2 * k2 + 1) * N + n4);
    float4 b_lo = *(const float4*)(w3 + (size_t)(2 * k2) * N + n4);
    float4 b_hi = *(const float4*)(w3 + (size_t)(2 * k2 + 1) * N + n4);
    __half2* op = out + (size_t)k2 * (2 * N) + 2 * n4;
    op[0] = __floats2half2_rn(a_lo.x, a_hi.x);
    op[1] = __floats2half2_rn(b_lo.x, b_hi.x);
    op[2] = __floats2half2_rn(a_lo.y, a_hi.y);
    op[3] = __floats2half2_rn(b_lo.y, b_hi.y);
    op[4] = __floats2half2_rn(a_lo.z, a_hi.z);
    op[5] = __floats2half2_rn(b_lo.z, b_hi.z);
    op[6] = __floats2half2_rn(a_lo.w, a_hi.w);
    op[7] = __floats2half2_rn(b_lo.w, b_hi.w);
}

// ---------------- activation convert: f32 -> f16 flat ------------------------
__global__ void ar_f2h(const float* __restrict__ in, __half2* __restrict__ out,
                       size_t n4) {
    size_t i = (size_t)blockIdx.x * blockDim.x + threadIdx.x;
    if (i < n4) {
        float4 v = ((const float4*)in)[i];
        out[2 * i]     = __floats2half2_rn(v.x, v.y);
        out[2 * i + 1] = __floats2half2_rn(v.z, v.w);
    }
}

// ---------------- reductions ------------------------------------------------
__device__ __forceinline__ float block_sum(float v, float* red) {
    int tid = threadIdx.x;
    #pragma unroll
    for (int o = 16; o > 0; o >>= 1) v += __shfl_xor_sync(0xffffffffu, v, o);
    if ((tid & 31) == 0) red[tid >> 5] = v;
    __syncthreads();
    if (tid == 0) {
        float s = red[0];
        int nw = blockDim.x >> 5;
        for (int i = 1; i < nw; i++) s += red[i];
        red[0] = s;
    }
    __syncthreads();
    float r = red[0];
    __syncthreads();
    return r;
}

// ---------------- rope frequency table --------------------------------------
__global__ void ar_freqs(float* __restrict__ fc) {
    int t = blockIdx.x * blockDim.x + threadIdx.x;
    if (t >= SEQ * 32) return;
    int p = t >> 5, j = t & 31;
    float c = 0.f, s = 0.f;
    if (p > 0) {                       // cls token keeps cos=sin=0 (ref!)
        int pp = p - 1, yy = pp >> 4, xx = pp & 15;
        int i = j & 15;
        float fr = powf(10000.0f, -(float)i * (1.0f / 16.0f));
        float tt = (j < 16) ? (float)yy : (float)xx;
        float ang = tt * fr;
        c = cosf(ang); s = sinf(ang);
    }
    fc[2 * t] = c;
    fc[2 * t + 1] = s;
}

// ---------------- assemble (cond | patch) + pos + LayerNorm ------------------
__global__ __launch_bounds__(256) void ar_assemble_ln(
    const float* __restrict__ patch, const float* __restrict__ condr,
    const float* __restrict__ pos, const float* __restrict__ g,
    const float* __restrict__ bta, float* __restrict__ h)
{
    __shared__ float buf[EMBED];
    __shared__ float red[8];
    int m = blockIdx.x, tid = threadIdx.x;
    int b = m / SEQ, s = m % SEQ;
    const float* src = (s == 0) ? (condr + (size_t)b * EMBED)
                                : (patch + ((size_t)(b * 256 + s - 1)) * EMBED);
    float lsum = 0.f;
    for (int d = tid; d < EMBED; d += 256) {
        float v = src[d] + pos[(size_t)s * EMBED + d];
        buf[d] = v; lsum += v;
    }
    float mean = block_sum(lsum, red) * (1.f / EMBED);
    float ls2 = 0.f;
    for (int d = tid; d < EMBED; d += 256) {
        float dv = buf[d] - mean; ls2 += dv * dv;
    }
    float var = block_sum(ls2, red) * (1.f / EMBED);
    float rinv = rsqrtf(var + 1e-6f);
    for (int d = tid; d < EMBED; d += 256)
        h[(size_t)m * EMBED + d] = (buf[d] - mean) * rinv * g[d] + bta[d];
}

// ---------------- RMSNorm (float4 loads, half output) ------------------------
__global__ __launch_bounds__(256) void ar_rmsnorm(
    const float* __restrict__ x, const float* __restrict__ w, __half* __restrict__ out)
{
    __shared__ float red[8];
    int m = blockIdx.x, tid = threadIdx.x;
    float4 v = ((const float4*)(x + (size_t)m * EMBED))[tid];
    float ss = v.x * v.x + v.y * v.y + v.z * v.z + v.w * v.w;
    ss = block_sum(ss, red);
    float r = rsqrtf(ss * (1.f / EMBED) + 1e-5f);
    float4 wv = ((const float4*)w)[tid];
    __half2* o2 = (__half2*)(out + (size_t)m * EMBED);
    o2[2 * tid]     = __floats2half2_rn(v.x * r * wv.x, v.y * r * wv.y);
    o2[2 * tid + 1] = __floats2half2_rn(v.z * r * wv.z, v.w * r * wv.w);
}

// ---------------- host orchestration ----------------------------------------
static inline void launch_gemm(const __half* A, const __half* B, const float* bias,
                               const float* res, float* C, int M, int N, int K) {
    dim3 grid(N / BN, (M + BM - 1) / BM);
    ar_gemm_f16<0><<<grid, 128, G_SMEM>>>(A, (const __half2*)B, bias, res, C,
                                          nullptr, nullptr, M, N, K);
}

static inline void launch_gemm_gu(const __half* A, const __half* B,
                                  __half* outH, int M, int N, int K) {
    dim3 grid(N / BN, (M + BM - 1) / BM);
    ar_gemm_f16<1><<<grid, 128, G_SMEM>>>(A, (const __half2*)B, nullptr, nullptr,
                                          nullptr, outH, nullptr, M, N, K);
}

static inline void launch_gemm_rope(const __half* A, const __half* B,
                                    __half* outH, const float* fc,
                                    int M, int N, int K) {
    dim3 grid(N / BN, (M + BM - 1) / BM);
    ar_gemm_f16<2><<<grid, 128, G_SMEM>>>(A, (const __half2*)B, nullptr, nullptr,
                                          nullptr, outH, fc, M, N, K);
}

static inline void launch_b2h(const float* in, __half* out, int K, int N, int L) {
    int total = (K / 2) * (N / 4);
    ar_b2h<<<dim3((total + 255) / 256, 1, L), 256>>>(in, (__half2*)out, K, N);
}

static inline void launch_f2h(const float* in, __half* out, size_t n) {
    size_t n4 = n / 4;
    ar_f2h<<<(unsigned)((n4 + 255) / 256), 256>>>(in, (__half2*)out, n4);
}

extern "C" void kernel_launch(void* const* d_in, const int* in_sizes, int n_in,
                              void* d_out, int out_size)
{
    const float* x       = (const float*)d_in[0];
    const float* cond    = (const float*)d_in[1];
    const float* patch_w = (const float*)d_in[2];
    const float* patch_b = (const float*)d_in[3];
    const float* ln_g    = (const float*)d_in[4];
    const float* ln_b    = (const float*)d_in[5];
    const float* pos     = (const float*)d_in[6];
    const float* cond_w  = (const float*)d_in[7];
    const float* cond_b  = (const float*)d_in[8];
    const float* wqkv    = (const float*)d_in[9];
    const float* wo      = (const float*)d_in[10];
    const float* w1      = (const float*)d_in[11];
    const float* w2      = (const float*)d_in[12];
    const float* w3      = (const float*)d_in[13];
    const float* anw     = (const float*)d_in[14];
    const float* fnw     = (const float*)d_in[15];
    float* h = (float*)d_out;

    __half *pa, *po, *pu, *pxh, *pch, *pwt;
    float *pqkv, *pf1, *pfc;
    cudaGetSymbolAddress((void**)&pa,   g_a);
    cudaGetSymbolAddress((void**)&po,   g_o);
    cudaGetSymbolAddress((void**)&pu,   g_u);
    cudaGetSymbolAddress((void**)&pxh,  g_xh);
    cudaGetSymbolAddress((void**)&pch,  g_ch);
    cudaGetSymbolAddress((void**)&pwt,  g_wt);
    cudaGetSymbolAddress((void**)&pqkv, g_qkv);
    cudaGetSymbolAddress((void**)&pf1,  g_f1);
    cudaGetSymbolAddress((void**)&pfc,  g_fc);

    __half* pqh = (__half*)pqkv;    // half view: roped qkv

    cudaFuncSetAttribute(ar_gemm_f16<0>, cudaFuncAttributeMaxDynamicSharedMemorySize,
                         G_SMEM);
    cudaFuncSetAttribute(ar_gemm_f16<1>, cudaFuncAttributeMaxDynamicSharedMemorySize,
                         G_SMEM);
    cudaFuncSetAttribute(ar_gemm_f16<2>, cudaFuncAttributeMaxDynamicSharedMemorySize,
                         G_SMEM);
    cudaFuncSetAttribute(ar_fattn, cudaFuncAttributeMaxDynamicSharedMemorySize,
                         ATT_SMEM);

    __half* qkvH   = pwt + OFF_QKV;
    __half* woH    = pwt + OFF_WO;
    __half* guH    = pwt + OFF_GU;
    __half* w2H    = pwt + OFF_W2;
    __half* patchH = pwt + OFF_PATCH;
    __half* condH  = pwt + OFF_COND;

    // convert weights + A-side raw inputs to half
    launch_b2h(wqkv,    qkvH,   1024, 3072, NB);
    launch_b2h(wo,      woH,    1024, 1024, NB);
    {   // merged gate-up interleave
        int total = (1024 / 2) * (HIDDEN / 4);
        ar_gu2h<<<dim3((total + 255) / 256, 1, NB), 256>>>(w1, w3, (__half2*)guH,
                                                           1024, HIDDEN);
    }
    launch_b2h(w2,      w2H,    HIDDEN, 1024, NB);
    launch_b2h(patch_w, patchH, 768, 1024, 1);
    launch_b2h(cond_w,  condH,  1024, 1024, 1);
    launch_f2h(x,    pxh, (size_t)8192 * 768);
    launch_f2h(cond, pch, (size_t)32 * 1024);

    // rope table
    ar_freqs<<<(SEQ * 32 + 255) / 256, 256>>>(pfc);
    // patch embed -> g_f1 (f32) ; cond embed -> g_qkv (f32, temp)
    launch_gemm(pxh, patchH, patch_b, nullptr, pf1, BATCH * 256, EMBED, 768);
    launch_gemm(pch, condH, cond_b, nullptr, pqkv, BATCH, EMBED, EMBED);
    // assemble + pos + layernorm -> h (d_out)
    ar_assemble_ln<<<MROWS, 256>>>(pf1, pqkv, pos, ln_g, ln_b, h);

    for (int l = 0; l < NB; l++) {
        __half* qkv_l = qkvH + (size_t)l * 1024 * 3072;
        __half* wo_l  = woH  + (size_t)l * 1024 * 1024;
        __half* gu_l  = guH  + (size_t)l * 1024 * (2 * HIDDEN);
        __half* w2_l  = w2H  + (size_t)l * HIDDEN * 1024;

        ar_rmsnorm<<<MROWS, 256>>>(h, anw + (size_t)l * EMBED, pa);
        launch_gemm_rope(pa, qkv_l, pqh, pfc, MROWS, 3 * EMBED, EMBED);
        ar_fattn<<<dim3(HEADS, BATCH), 128, ATT_SMEM>>>(pqh, po);
        launch_gemm(po, wo_l, nullptr, h, h, MROWS, EMBED, EMBED);

        ar_rmsnorm<<<MROWS, 256>>>(h, fnw + (size_t)l * EMBED, pa);
        // merged gate-up GEMM: silu(gate)*up in-register -> half u
        launch_gemm_gu(pa, gu_l, pu, MROWS, 2 * HIDDEN, EMBED);
        launch_gemm(pu, w2_l, nullptr, h, h, MROWS, EMBED, HIDDEN);
    }
}